// round 13
// baseline (speedup 1.0000x reference)
#include <cuda_runtime.h>
#include <cuda_bf16.h>
#include <math.h>
#include <stdint.h>

#define B_  32
#define N_  64
#define S_  9
#define C_  128
#define CS_ 32
#define AVGF 49.0f
#define TILES (B_*32)
#define XBYTES (B_*N_*384*sizeof(float))

// ---------------- device scratch ----------------
__device__ __nv_bfloat16 g_Ahi[TILES*16384], g_Alo[TILES*16384];
__device__ __nv_bfloat16 g_Bhi[TILES*16384], g_Blo[TILES*16384];
__device__ float g_X0[B_*N_*384];
__device__ float g_X1[B_*N_*384];
__device__ uint4 g_Bf[13*4096];
__device__ __nv_bfloat16 g_WpHi[4*147456], g_WpLo[4*147456];
__device__ float g_y012[B_*N_*3*CS_];
__device__ float g_y34[B_*2*CS_];
__device__ float g_Vrow[B_*N_*C_];
__device__ float g_Vcol[B_*N_*C_];
__device__ float g_Dd[B_*N_*C_];
__device__ float g_G[B_*C_];
__device__ float g_E[B_*C_];
__device__ float g_dg[B_*C_];
__device__ float g_tot[B_*C_];

__device__ __forceinline__ float lrelu(float x){ return x >= 0.f ? x : 0.01f*x; }
__device__ __forceinline__ uint32_t smem_u32(const void* p) {
    uint32_t a;
    asm("{ .reg .u64 t; cvta.to.shared.u64 t, %1; cvt.u32.u64 %0, t; }" : "=r"(a) : "l"(p));
    return a;
}
__device__ __forceinline__ void split2(float v, __nv_bfloat16& h, __nv_bfloat16& l) {
    h = __float2bfloat16(v);
    l = __float2bfloat16(v - __bfloat162float(h));
}
__device__ __forceinline__ uint32_t packbf(__nv_bfloat16 a, __nv_bfloat16 b) {
    __nv_bfloat162 p; p.x = a; p.y = b;
    return *(uint32_t*)&p;
}
__device__ __forceinline__ void ldmx4(uint32_t a, uint32_t& r0, uint32_t& r1, uint32_t& r2, uint32_t& r3) {
    asm volatile("ldmatrix.sync.aligned.m8n8.x4.shared.b16 {%0,%1,%2,%3}, [%4];"
                 : "=r"(r0), "=r"(r1), "=r"(r2), "=r"(r3) : "r"(a));
}
__device__ __forceinline__ void mma16816(float* c, const uint32_t* a, uint32_t b0, uint32_t b1) {
    asm volatile("mma.sync.aligned.m16n8k16.row.col.f32.bf16.bf16.f32 "
                 "{%0,%1,%2,%3}, {%4,%5,%6,%7}, {%8,%9}, {%0,%1,%2,%3};"
                 : "+f"(c[0]), "+f"(c[1]), "+f"(c[2]), "+f"(c[3])
                 : "r"(a[0]), "r"(a[1]), "r"(a[2]), "r"(a[3]), "r"(b0), "r"(b1));
}
#define CPA16(dst, src) asm volatile("cp.async.ca.shared.global [%0], [%1], 16;" :: "r"(dst), "l"(src))
#define CPCOMMIT() asm volatile("cp.async.commit_group;" ::: "memory")
#define CPWAIT1()  asm volatile("cp.async.wait_group 1;"  ::: "memory")
#define CPWAIT()   asm volatile("cp.async.wait_group 0;"  ::: "memory")

#define ALO2  34816
#define SM_G  69632
#define APAD 72
#define BPAD 80
#define AH_OFF 0
#define AL_OFF 18432
#define BH_OFF 36864
#define BL_OFF 57344
#define SM_P 77824

// ---------------- one-time setup ----------------
__global__ void k_setup(const float* __restrict__ m0, const float* __restrict__ m1,
                        const float* __restrict__ m2, const float* __restrict__ m3,
                        const float* __restrict__ e0, const float* __restrict__ e1,
                        const float* __restrict__ e2, const float* __restrict__ e3,
                        const float* __restrict__ wfin,
                        const float* __restrict__ scalars, const int* __restrict__ nobj,
                        const float* __restrict__ w_in) {
    int blk = blockIdx.x, tid = threadIdx.x;
    if (blk < 52) {
        int mat = blk >> 2, quar = blk & 3;
        const float* W;
        if (mat < 4)       W = (mat==0)?m0:(mat==1)?m1:(mat==2)?m2:m3;
        else if (mat < 12) {
            int l = (mat-4)>>1, wh = (mat-4)&1;
            const float* E = (l==0)?e0:(l==1)?e1:(l==2)?e2:e3;
            W = E + wh*16384;
        } else W = wfin;
        uint4* dst = g_Bf + mat*4096;
        for (int e = quar*1024 + tid; e < quar*1024 + 1024; e += 256) {
            int lane = e&31, nt = (e>>5)&7, ks = (e>>8)&7, wx = e>>11;
            int n = wx*64 + nt*8 + (lane>>2);
            int k0 = ks*16 + (lane&3)*2;
            __nv_bfloat16 h00,l00,h01,l01,h10,l10,h11,l11;
            split2(W[k0*128+n],     h00, l00);
            split2(W[(k0+1)*128+n], h01, l01);
            split2(W[(k0+8)*128+n], h10, l10);
            split2(W[(k0+9)*128+n], h11, l11);
            uint4 o;
            o.x = packbf(h00,h01); o.y = packbf(h10,h11);
            o.z = packbf(l00,l01); o.w = packbf(l10,l11);
            dst[e] = o;
        }
    } else if (blk < 100) {
        int idx = blk - 52;
        int unit = idx >> 2, quar = idx & 3;
        int l = unit / 3, p = unit % 3;
        const int tbl[3][3] = {{3,5,7},{4,6,8},{2,9,10}};
        const float* E = (l==0)?e0:(l==1)?e1:(l==2)?e2:e3;
        __nv_bfloat16* Hi = g_WpHi + (size_t)l*147456 + p*49152;
        __nv_bfloat16* Lo = g_WpLo + (size_t)l*147456 + p*49152;
        for (int e = quar*12288 + tid; e < quar*12288 + 12288; e += 256) {
            int n = e / 384, k = e % 384;
            int mat = tbl[p][k>>7], kk = k&127;
            __nv_bfloat16 h, lo;
            split2(E[(mat*C_ + kk)*C_ + n], h, lo);
            Hi[n*384 + k] = h; Lo[n*384 + k] = lo;
        }
    } else {
        int b = blk - 100;
        __shared__ float xs[N_][S_];
        __shared__ float ssum[S_];
        int nb = nobj[b];
        for (int idx = tid; idx < N_*S_; idx += 256) {
            int n = idx/S_, s = idx%S_;
            xs[n][s] = (n < nb) ? scalars[(b*N_+n)*S_+s] : 0.f;
        }
        __syncthreads();
        if (tid < S_) {
            float a = 0.f;
            for (int n = 0; n < N_; n++) a += xs[n][tid];
            ssum[tid] = a / AVGF;
        }
        __syncthreads();
        for (int idx = tid; idx < N_*CS_; idx += 256) {
            int n = idx/CS_, c = idx%CS_;
            float a0=0, a1=0, a2=0;
            #pragma unroll
            for (int s = 0; s < S_; s++) {
                float xv = xs[n][s];
                a0 += xv*w_in[(0*S_+s)*CS_+c];
                a1 += xv*w_in[(1*S_+s)*CS_+c];
                a2 += xv*w_in[(2*S_+s)*CS_+c];
            }
            g_y012[((b*N_+n)*3+0)*CS_+c] = a0;
            g_y012[((b*N_+n)*3+1)*CS_+c] = a1;
            g_y012[((b*N_+n)*3+2)*CS_+c] = a2;
        }
        if (tid < 2*CS_) {
            int k = tid/CS_, c = tid%CS_;
            float a = 0.f;
            #pragma unroll
            for (int s = 0; s < S_; s++) a += ssum[s]*w_in[((3+k)*S_+s)*CS_+c];
            g_y34[(b*2+k)*CS_+c] = a;
        }
    }
}

// ---------------- GEMM helpers ----------------
struct GemmCtx {
    uint32_t sb;
    int tid, wid, lane, tile, b, i0, nb;
    int wy, wx, rb, nb0, lrow, lcolb, g, t2;
};
__device__ __forceinline__ void stage_src(const GemmCtx& X, const __nv_bfloat16* Ahi,
                                          const __nv_bfloat16* Alo, bool transp) {
    #pragma unroll
    for (int uu = 0; uu < 16; uu++) {
        int group = uu>>3, comp = (uu>>2)&1, sub = uu&3;
        int f = X.tid + 256*(comp*8 + group*4 + sub);
        int idx = f & 2047;
        int row = (idx>>3)&127, c8 = idx&7, c16 = group*8 + c8;
        const __nv_bfloat16* basep = comp ? Alo : Ahi;
        size_t goff;
        if (!transp) {
            goff = (size_t)X.tile*16384 + row*128 + c16*8;
        } else {
            int jj = row&63, hh = row>>6;
            goff = ((size_t)(X.b*32 + (jj>>1))*128 + (jj&1)*64 + X.i0 + hh)*128 + c16*8;
        }
        uint32_t dst = X.sb + comp*ALO2 + row*272 + c16*16;
        CPA16(dst, basep + goff);
        if (uu == 7) CPCOMMIT();
    }
    CPCOMMIT();
}
__device__ __forceinline__ void compute_pass(const GemmCtx& X, const uint4* Fw,
                                             float c[2][8][4], bool staged) {
    #pragma unroll
    for (int half = 0; half < 2; half++) {
        if (staged) { if (half == 0) CPWAIT1(); else CPWAIT(); __syncthreads(); }
        #pragma unroll
        for (int ks = half*4; ks < half*4+4; ks++) {
            uint32_t ah[2][4], al[2][4];
            #pragma unroll
            for (int mt = 0; mt < 2; mt++) {
                uint32_t adr = X.sb + (X.rb + mt*16 + X.lrow)*272 + ks*32 + X.lcolb;
                ldmx4(adr, ah[mt][0], ah[mt][1], ah[mt][2], ah[mt][3]);
                adr += ALO2;
                ldmx4(adr, al[mt][0], al[mt][1], al[mt][2], al[mt][3]);
            }
            uint4 f4 = Fw[(ks*8)*32 + X.lane];
            #pragma unroll
            for (int nt = 0; nt < 8; nt++) {
                uint4 cur = f4;
                if (nt < 7) f4 = Fw[(ks*8 + nt + 1)*32 + X.lane];
                #pragma unroll
                for (int mt = 0; mt < 2; mt++) {
                    mma16816(c[mt][nt], ah[mt], cur.x, cur.y);
                    mma16816(c[mt][nt], ah[mt], cur.z, cur.w);
                    mma16816(c[mt][nt], al[mt], cur.x, cur.y);
                }
            }
        }
    }
}
__device__ __forceinline__ void init_ctx(GemmCtx& X, unsigned char* sm) {
    X.sb = smem_u32(sm);
    X.tid = threadIdx.x; X.wid = X.tid>>5; X.lane = X.tid&31;
    X.tile = blockIdx.x; X.b = X.tile>>5; X.i0 = (X.tile&31)<<1;
    X.wy = X.wid&3; X.wx = X.wid>>2;
    X.rb = X.wy*32; X.nb0 = X.wx*64;
    X.lrow = (X.lane&7) + ((X.lane>>3)&1)*8;
    X.lcolb = ((X.lane>>4)&1)*16;
    X.g = X.lane>>2; X.t2 = (X.lane&3)*2;
}
#define ZEROC(c) { _Pragma("unroll") for (int mt=0;mt<2;mt++) _Pragma("unroll") for (int nt=0;nt<8;nt++) _Pragma("unroll") for (int q=0;q<4;q++) c[mt][nt][q]=0.f; }

// epilogue: write U (bf16 hi/lo) + accumulate reductions into Xout
__device__ __forceinline__ void epilogue_UX(const GemmCtx& X, float c[2][8][4],
                                            const float* bias,
                                            __nv_bfloat16* OutHi, __nv_bfloat16* OutLo,
                                            float* Xout, unsigned char* sm) {
    __syncthreads();
    float* Vs = (float*)sm;   // [128][132]
    __nv_bfloat16* Hi = OutHi + (size_t)X.tile*16384;
    __nv_bfloat16* Lo = OutLo + (size_t)X.tile*16384;
    #pragma unroll
    for (int mt = 0; mt < 2; mt++)
        #pragma unroll
        for (int h = 0; h < 2; h++) {
            int row = X.rb + mt*16 + X.g + h*8;
            int i = X.i0 + (row>>6), j = row&63;
            float mask = (i < X.nb && j < X.nb) ? 1.f : 0.f;
            #pragma unroll
            for (int nt = 0; nt < 8; nt++) {
                int col = X.nb0 + nt*8 + X.t2;
                float vx = lrelu(c[mt][nt][h*2+0] + bias[col])   * mask;
                float vy = lrelu(c[mt][nt][h*2+1] + bias[col+1]) * mask;
                __nv_bfloat16 hx,lx,hy,ly;
                split2(vx, hx, lx); split2(vy, hy, ly);
                *(uint32_t*)(Hi + row*128 + col) = packbf(hx, hy);
                *(uint32_t*)(Lo + row*128 + col) = packbf(lx, ly);
                float2 v; v.x = vx; v.y = vy;
                *(float2*)(Vs + row*132 + col) = v;
            }
        }
    __syncthreads();
    int t = X.tid;
    {
        int half = t >> 7, cc = t & 127;
        float s = 0.f;
        #pragma unroll 8
        for (int r = 0; r < 64; r++) s += Vs[(half*64 + r)*132 + cc];
        size_t m = (size_t)(X.b*64 + X.i0 + half);
        Xout[m*384 + 128 + cc] = s / AVGF;
        Xout[m*384 + cc] = Vs[(half*64 + X.i0 + half)*132 + cc];
    }
    #pragma unroll
    for (int u = 0; u < 32; u++) {
        int e = t + 256*u;
        int j = e >> 7, cc = e & 127;
        float v = (Vs[j*132 + cc] + Vs[(64 + j)*132 + cc]) / AVGF;
        if (v != 0.f)
            atomicAdd(&Xout[(size_t)(X.b*64 + j)*384 + 256 + cc], v);
    }
}

// ---------------- mode-0 GEMM: U = lrelu(A@W + b)*mask, + X reductions ----------------
__global__ void __launch_bounds__(256, 2) k_gemm0(const __nv_bfloat16* __restrict__ Ahi,
                                                  const __nv_bfloat16* __restrict__ Alo,
                                                  const uint4* __restrict__ F,
                                                  const float* __restrict__ bias,
                                                  const int* __restrict__ nobj,
                                                  __nv_bfloat16* __restrict__ OutHi,
                                                  __nv_bfloat16* __restrict__ OutLo,
                                                  float* __restrict__ Xout) {
    extern __shared__ unsigned char sm[];
    GemmCtx X; init_ctx(X, sm);
    X.nb = nobj[X.b];
    if (X.i0 >= X.nb) return;
    float c[2][8][4]; ZEROC(c);
    stage_src(X, Ahi, Alo, false);
    compute_pass(X, F + X.wx*2048, c, true);
    epilogue_UX(X, c, bias, OutHi, OutLo, Xout, sm);
}

// ---------------- fused GEMM: Eq2to2 dual + combine -> T(smem) -> next GEMM ----------
__global__ void __launch_bounds__(256, 2) k_gemm2(const __nv_bfloat16* __restrict__ Uhi,
                                                  const __nv_bfloat16* __restrict__ Ulo,
                                                  const uint4* __restrict__ F0,
                                                  const uint4* __restrict__ F1,
                                                  const uint4* __restrict__ F2,
                                                  const float* __restrict__ bias2,
                                                  const int* __restrict__ nobj, int mode2,
                                                  __nv_bfloat16* __restrict__ OutHi,
                                                  __nv_bfloat16* __restrict__ OutLo,
                                                  float* __restrict__ Xout) {
    extern __shared__ unsigned char sm[];
    GemmCtx X; init_ctx(X, sm);
    X.nb = nobj[X.b];
    if (X.i0 >= X.nb) return;
    float c[2][8][4]; ZEROC(c);
    stage_src(X, Uhi, Ulo, false);
    compute_pass(X, F0 + X.wx*2048, c, true);
    __syncthreads();
    stage_src(X, Uhi, Ulo, true);
    compute_pass(X, F1 + X.wx*2048, c, true);
    __syncthreads();
    #pragma unroll
    for (int mt = 0; mt < 2; mt++)
        #pragma unroll
        for (int h = 0; h < 2; h++) {
            int row = X.rb + mt*16 + X.g + h*8;
            int i = X.i0 + (row>>6), j = row&63;
            float mask = (i < X.nb && j < X.nb) ? 1.f : 0.f;
            bool diag = (i == j);
            const float* vr = g_Vrow + (X.b*64+i)*C_;
            const float* vc = g_Vcol + (X.b*64+j)*C_;
            const float* gg = g_G + X.b*C_;
            const float* dd = g_Dd + (X.b*64+i)*C_;
            const float* ee = g_E + X.b*C_;
            #pragma unroll
            for (int nt = 0; nt < 8; nt++) {
                int col = X.nb0 + nt*8 + X.t2;
                float vx = c[mt][nt][h*2+0] + vr[col]   + gg[col]   + vc[col];
                float vy = c[mt][nt][h*2+1] + vr[col+1] + gg[col+1] + vc[col+1];
                if (diag) { vx += dd[col] + ee[col]; vy += dd[col+1] + ee[col+1]; }
                vx = lrelu(vx) * mask;
                vy = lrelu(vy) * mask;
                __nv_bfloat16 hx,lx,hy,ly;
                split2(vx, hx, lx); split2(vy, hy, ly);
                *(uint32_t*)(sm + row*272 + col*2)        = packbf(hx, hy);
                *(uint32_t*)(sm + ALO2 + row*272 + col*2) = packbf(lx, ly);
            }
        }
    __syncthreads();
    ZEROC(c);
    compute_pass(X, F2 + X.wx*2048, c, false);
    if (mode2 == 0) {
        epilogue_UX(X, c, bias2, OutHi, OutLo, Xout, sm);
    } else {
        __syncthreads();
        float* Vs = (float*)sm;
        #pragma unroll
        for (int mt = 0; mt < 2; mt++)
            #pragma unroll
            for (int h = 0; h < 2; h++) {
                int row = X.rb + mt*16 + X.g + h*8;
                int i = X.i0 + (row>>6), j = row&63;
                float mask = (i < X.nb && j < X.nb) ? 1.f : 0.f;
                #pragma unroll
                for (int nt = 0; nt < 8; nt++) {
                    int col = X.nb0 + nt*8 + X.t2;
                    float2 v;
                    v.x = lrelu(c[mt][nt][h*2+0] + bias2[col])   * mask;
                    v.y = lrelu(c[mt][nt][h*2+1] + bias2[col+1]) * mask;
                    *(float2*)(Vs + row*132 + col) = v;
                }
            }
        __syncthreads();
        if (X.tid < 128) {
            float s = 0.f;
            #pragma unroll 8
            for (int r = 0; r < 128; r++) s += Vs[r*132 + X.tid];
            atomicAdd(&g_tot[X.b*C_ + X.tid], s);
            float dgv = Vs[X.i0*132 + X.tid] + Vs[(64 + X.i0 + 1)*132 + X.tid];
            atomicAdd(&g_dg[X.b*C_ + X.tid], dgv);
        }
    }
}

// ---------------- projection GEMM + fused G/E ----------------
__global__ void __launch_bounds__(256, 2) k_proj(const __nv_bfloat16* __restrict__ Bhi,
                                                 const __nv_bfloat16* __restrict__ Blo,
                                                 const float* __restrict__ W,
                                                 const float* __restrict__ eqb,
                                                 const float* __restrict__ eqbd,
                                                 const int* __restrict__ nobj,
                                                 const float* __restrict__ Xin) {
    extern __shared__ unsigned char sm[];
    if (blockIdx.x >= 48) {
        int b = blockIdx.x - 48, d = threadIdx.x;
        float* tt = (float*)sm;
        float* tg = (float*)sm + 128;
        if (d < 128) {
            int nb = nobj[b];
            float t = 0.f, tr = 0.f;
            for (int i = 0; i < nb; i++) {
                size_t m = (size_t)(b*N_+i);
                t  += Xin[m*384 + 128 + d];
                tr += Xin[m*384 + d];
            }
            tt[d] = t / AVGF; tg[d] = tr / AVGF;
        }
        __syncthreads();
        if (d < 128) {
            float g = eqb[d], e = eqbd[d];
            for (int c = 0; c < C_; c++) {
                g += tt[c]*W[(11*C_+c)*C_+d] + tg[c]*W[(13*C_+c)*C_+d];
                e += tt[c]*W[(12*C_+c)*C_+d] + tg[c]*W[(14*C_+c)*C_+d];
            }
            g_G[b*C_+d] = g; g_E[b*C_+d] = e;
        }
        return;
    }
    uint32_t sb = smem_u32(sm);
    int tid = threadIdx.x, wid = tid>>5, lane = tid&31;
    int p = blockIdx.x >> 4, tile = blockIdx.x & 15;
    int wy = wid&3, wx = wid>>2;
    int rb = wy*32, nb0 = wx*64;
    float c[2][8][4]; ZEROC(c);
    int lrow = (lane&7) + ((lane>>3)&1)*8;
    int lcolb = ((lane>>4)&1)*16;
    int bn = nb0 + (lane>>2);
    int btid4 = (lane&3)*4;
    const uint32_t* bhp = (const uint32_t*)(Bhi + p*49152);
    const uint32_t* blp = (const uint32_t*)(Blo + p*49152);
    const float4* Ag = (const float4*)(Xin + (size_t)tile*128*384);
    for (int ph = 0; ph < 6; ph++) {
        if (ph) __syncthreads();
        #pragma unroll
        for (int u = 0; u < 8; u++) {
            int f = tid + 256*u;
            int row = f>>4, q = f&15, c4 = q*4;
            float4 v = Ag[row*96 + ph*16 + q];
            __nv_bfloat16 h[4], l[4];
            split2(v.x, h[0], l[0]); split2(v.y, h[1], l[1]);
            split2(v.z, h[2], l[2]); split2(v.w, h[3], l[3]);
            *(uint2*)(sm + AH_OFF + (row*APAD + c4)*2) = *(uint2*)h;
            *(uint2*)(sm + AL_OFF + (row*APAD + c4)*2) = *(uint2*)l;
        }
        #pragma unroll
        for (int u = 0; u < 16; u++) {
            int f = tid + 256*u;
            int n = f>>5, kp = f&31;
            int k = kp*2;
            int col = (k & ~15) + (((k>>1)&3)<<2) + (((k>>3)&1)<<1);
            *(uint32_t*)(sm + BH_OFF + (n*BPAD + col)*2) = bhp[n*192 + ph*32 + kp];
            *(uint32_t*)(sm + BL_OFF + (n*BPAD + col)*2) = blp[n*192 + ph*32 + kp];
        }
        __syncthreads();
        #pragma unroll
        for (int ks = 0; ks < 4; ks++) {
            uint32_t ah[2][4], al[2][4];
            #pragma unroll
            for (int mt = 0; mt < 2; mt++) {
                uint32_t adr = sb + AH_OFF + (rb + mt*16 + lrow)*APAD*2 + ks*32 + lcolb;
                ldmx4(adr, ah[mt][0], ah[mt][1], ah[mt][2], ah[mt][3]);
                adr = sb + AL_OFF + (rb + mt*16 + lrow)*APAD*2 + ks*32 + lcolb;
                ldmx4(adr, al[mt][0], al[mt][1], al[mt][2], al[mt][3]);
            }
            #pragma unroll
            for (int nt = 0; nt < 8; nt++) {
                uint32_t bh0, bh1, bl0, bl1;
                uint32_t badr = sb + BH_OFF + ((bn + nt*8)*BPAD + ks*16 + btid4)*2;
                asm volatile("ld.shared.v2.b32 {%0,%1}, [%2];" : "=r"(bh0), "=r"(bh1) : "r"(badr));
                badr = sb + BL_OFF + ((bn + nt*8)*BPAD + ks*16 + btid4)*2;
                asm volatile("ld.shared.v2.b32 {%0,%1}, [%2];" : "=r"(bl0), "=r"(bl1) : "r"(badr));
                #pragma unroll
                for (int mt = 0; mt < 2; mt++) {
                    mma16816(c[mt][nt], ah[mt], bh0, bh1);
                    mma16816(c[mt][nt], ah[mt], bl0, bl1);
                    mma16816(c[mt][nt], al[mt], bh0, bh1);
                }
            }
        }
    }
    float* Out = (p==0) ? g_Vrow : (p==1) ? g_Vcol : g_Dd;
    int g = lane>>2, t2 = (lane&3)*2;
    #pragma unroll
    for (int mt = 0; mt < 2; mt++)
        #pragma unroll
        for (int h = 0; h < 2; h++) {
            int row = rb + mt*16 + g + h*8;
            int m = tile*128 + row;
            #pragma unroll
            for (int nt = 0; nt < 8; nt++) {
                int col = nb0 + nt*8 + t2;
                float2 v;
                v.x = c[mt][nt][h*2+0];
                v.y = c[mt][nt][h*2+1];
                *(float2*)(Out + (size_t)m*128 + col) = v;
            }
        }
}

// ---------------- initial T ----------------
__global__ void k_init(const float* __restrict__ momenta, const int* __restrict__ nobj,
                       const float* __restrict__ w_lin, const float* __restrict__ alpha,
                       const float* __restrict__ b_in) {
    int b = blockIdx.x / N_, i = blockIdx.x % N_;
    int nb = nobj[b];
    if (i >= nb) return;
    int tid = threadIdx.x;
    int c = tid & 127, jh = tid >> 7;
    __shared__ float pm[N_][4];
    __shared__ float dij[N_];
    __shared__ float y1s[N_][CS_];
    __shared__ float y0r[CS_], y2r[CS_], y3s[CS_], y4s[CS_];
    if (tid < 256) pm[tid>>2][tid&3] = momenta[(b*N_)*4 + tid];
    for (int idx = tid; idx < N_*CS_; idx += 256) {
        int n = idx/CS_, cs = idx%CS_;
        y1s[n][cs] = g_y012[((b*N_+n)*3+1)*CS_+cs];
    }
    if (tid < CS_) {
        y0r[tid] = g_y012[((b*N_+i)*3+0)*CS_+tid];
        y2r[tid] = g_y012[((b*N_+i)*3+2)*CS_+tid];
    } else if (tid < 2*CS_) {
        y3s[tid-CS_] = g_y34[(b*2+0)*CS_+tid-CS_];
    } else if (tid < 3*CS_) {
        y4s[tid-2*CS_] = g_y34[(b*2+1)*CS_+tid-2*CS_];
    }
    __syncthreads();
    if (tid < N_)
        dij[tid] = pm[i][0]*pm[tid][0] - pm[i][1]*pm[tid][1]
                 - pm[i][2]*pm[tid][2] - pm[i][3]*pm[tid][3];
    __syncthreads();
    float base = 0.f, wl = 0.f, al = 0.f;
    if (c < CS_) base = y0r[c] + y3s[c] + b_in[c];
    else { wl = w_lin[c-CS_]; al = alpha[c-CS_]; }
    size_t rowbase = ((size_t)(b*32 + (i>>1))*128 + (i&1)*64)*128;
    for (int j = jh; j < N_; j += 2) {
        float mask = (j < nb) ? 1.f : 0.f;
        float v;
        if (c < CS_) {
            v = base + y1s[j][c];
            if (j == i) v += y2r[c] + y4s[c];
            v = lrelu(v) * mask;
        } else {
            float r = dij[j] * wl;
            v = al * copysignf(log1pf(fabsf(r)), r) * mask;
        }
        __nv_bfloat16 h, l;
        split2(v, h, l);
        g_Ahi[rowbase + j*128 + c] = h;
        g_Alo[rowbase + j*128 + c] = l;
    }
}

// ---------------- output head (resets accumulators) ----------------
__global__ void k_out(const float* __restrict__ w20, const float* __restrict__ b20,
                      const float* __restrict__ wmlp, const float* __restrict__ bmlp,
                      float* __restrict__ out) {
    int b = blockIdx.x, d = threadIdx.x;
    __shared__ float a0[C_], a1[C_], act[C_];
    a0[d] = lrelu(g_dg[b*C_+d] / AVGF);
    a1[d] = lrelu(g_tot[b*C_+d] / (AVGF*AVGF));
    g_dg[b*C_+d] = 0.f;
    g_tot[b*C_+d] = 0.f;
    __syncthreads();
    float a = b20[d];
    for (int c = 0; c < C_; c++) a += a0[c]*w20[c*C_+d] + a1[c]*w20[(C_+c)*C_+d];
    act[d] = a;
    __syncthreads();
    if (d < 2) {
        float o = bmlp[d];
        for (int k = 0; k < C_; k++) o += act[k]*wmlp[k*2+d];
        out[b*2+d] = o;
    }
}

// ---------------- host ----------------
extern "C" void kernel_launch(void* const* d_in, const int* in_sizes, int n_in,
                              void* d_out, int out_size) {
    const float *momenta=0, *scalars=0, *w_lin=0, *alpha=0, *w_in=0, *b_in=0;
    const int* nobj=0;
    const float *msgw[4], *msgb[4], *eqw[4], *eqb[4], *eqbd[4];
    const float *wm0=0, *bm0=0, *w20=0, *b20=0, *wmlp=0, *bmlp=0;

    if (n_in >= 33 && in_sizes[0] == 8192) {
        momenta=(const float*)d_in[0]; scalars=(const float*)d_in[1]; nobj=(const int*)d_in[2];
        w_lin=(const float*)d_in[3]; alpha=(const float*)d_in[4]; w_in=(const float*)d_in[5];
        b_in=(const float*)d_in[6];
        for (int l = 0; l < 4; l++) {
            msgw[l]=(const float*)d_in[7+l];  msgb[l]=(const float*)d_in[11+l];
            eqw[l] =(const float*)d_in[15+l]; eqb[l] =(const float*)d_in[19+l];
            eqbd[l]=(const float*)d_in[23+l];
        }
        wm0=(const float*)d_in[27]; bm0=(const float*)d_in[28]; w20=(const float*)d_in[29];
        b20=(const float*)d_in[30]; wmlp=(const float*)d_in[31]; bmlp=(const float*)d_in[32];
    } else if (n_in >= 33) {
        alpha=(const float*)d_in[0]; b20=(const float*)d_in[1]; b_in=(const float*)d_in[2];
        bm0=(const float*)d_in[3]; bmlp=(const float*)d_in[4];
        for (int l = 0; l < 4; l++) {
            eqb[l] =(const float*)d_in[5+l];  eqbd[l]=(const float*)d_in[9+l];
            eqw[l] =(const float*)d_in[13+l]; msgb[l]=(const float*)d_in[18+l];
            msgw[l]=(const float*)d_in[22+l];
        }
        momenta=(const float*)d_in[17]; nobj=(const int*)d_in[26]; scalars=(const float*)d_in[27];
        w20=(const float*)d_in[28]; w_in=(const float*)d_in[29]; w_lin=(const float*)d_in[30];
        wm0=(const float*)d_in[31]; wmlp=(const float*)d_in[32];
    } else {
        momenta=(const float*)d_in[0]; scalars=(const float*)d_in[1]; nobj=(const int*)d_in[2];
        w_lin=(const float*)d_in[3]; alpha=(const float*)d_in[4]; w_in=(const float*)d_in[5];
        b_in=(const float*)d_in[6];
        for (int l = 0; l < 4; l++) {
            msgw[l]=(const float*)d_in[7]+(size_t)l*C_*C_;     msgb[l]=(const float*)d_in[8]+(size_t)l*C_;
            eqw[l] =(const float*)d_in[9]+(size_t)l*15*C_*C_;  eqb[l] =(const float*)d_in[10]+(size_t)l*C_;
            eqbd[l]=(const float*)d_in[11]+(size_t)l*C_;
        }
        wm0=(const float*)d_in[12]; bm0=(const float*)d_in[13]; w20=(const float*)d_in[14];
        b20=(const float*)d_in[15]; wmlp=(const float*)d_in[16]; bmlp=(const float*)d_in[17];
    }

    cudaFuncSetAttribute(k_gemm0, cudaFuncAttributeMaxDynamicSharedMemorySize, SM_G);
    cudaFuncSetAttribute(k_gemm2, cudaFuncAttributeMaxDynamicSharedMemorySize, SM_G);
    cudaFuncSetAttribute(k_proj,  cudaFuncAttributeMaxDynamicSharedMemorySize, SM_P);

    __nv_bfloat16 *Ahi=0, *Alo=0, *Bhi=0, *Blo=0, *WpH=0, *WpL=0;
    uint4* Bf=0;
    float *X0=0, *X1=0;
    cudaGetSymbolAddress((void**)&Ahi, g_Ahi);
    cudaGetSymbolAddress((void**)&Alo, g_Alo);
    cudaGetSymbolAddress((void**)&Bhi, g_Bhi);
    cudaGetSymbolAddress((void**)&Blo, g_Blo);
    cudaGetSymbolAddress((void**)&Bf,  g_Bf);
    cudaGetSymbolAddress((void**)&WpH, g_WpHi);
    cudaGetSymbolAddress((void**)&WpL, g_WpLo);
    cudaGetSymbolAddress((void**)&X0,  g_X0);
    cudaGetSymbolAddress((void**)&X1,  g_X1);

    k_setup<<<132, 256>>>(msgw[0], msgw[1], msgw[2], msgw[3],
                          eqw[0], eqw[1], eqw[2], eqw[3], wm0,
                          scalars, nobj, w_in);
    k_init<<<B_*N_, 256>>>(momenta, nobj, w_lin, alpha, b_in);

    cudaMemsetAsync(X0, 0, XBYTES);
    k_gemm0<<<TILES, 256, SM_G>>>(Ahi, Alo, Bf + 0*4096, msgb[0], nobj, Bhi, Blo, X0);

    __nv_bfloat16 *curHi = Bhi, *curLo = Blo, *nxtHi = Ahi, *nxtLo = Alo;
    float *Xcur = X0, *Xnxt = X1;
    for (int l = 0; l < 4; l++) {
        k_proj<<<80, 256, SM_P>>>(WpH + (size_t)l*147456, WpL + (size_t)l*147456,
                                  eqw[l], eqb[l], eqbd[l], nobj, Xcur);
        if (l < 3) {
            cudaMemsetAsync(Xnxt, 0, XBYTES);
            k_gemm2<<<TILES, 256, SM_G>>>(curHi, curLo,
                                          Bf + (4 + l*2)*4096, Bf + (5 + l*2)*4096,
                                          Bf + (l+1)*4096, msgb[l+1], nobj, 0,
                                          nxtHi, nxtLo, Xnxt);
            __nv_bfloat16* th = curHi; curHi = nxtHi; nxtHi = th;
            __nv_bfloat16* tl = curLo; curLo = nxtLo; nxtLo = tl;
            float* tx = Xcur; Xcur = Xnxt; Xnxt = tx;
        } else {
            k_gemm2<<<TILES, 256, SM_G>>>(curHi, curLo,
                                          Bf + (4 + l*2)*4096, Bf + (5 + l*2)*4096,
                                          Bf + 12*4096, bm0, nobj, 3,
                                          (__nv_bfloat16*)0, (__nv_bfloat16*)0, (float*)0);
        }
    }

    k_out<<<B_, 128>>>(w20, b20, wmlp, bmlp, (float*)d_out);
}

// round 14
// speedup vs baseline: 1.0898x; 1.0898x over previous
#include <cuda_runtime.h>
#include <cuda_bf16.h>
#include <math.h>
#include <stdint.h>

#define B_  32
#define N_  64
#define S_  9
#define C_  128
#define CS_ 32
#define AVGF 49.0f
#define TILES (B_*32)

// ---------------- device scratch ----------------
__device__ __nv_bfloat16 g_Ahi[TILES*16384], g_Alo[TILES*16384];
__device__ __nv_bfloat16 g_Bhi[TILES*16384], g_Blo[TILES*16384];
__device__ __nv_bfloat16 g_Xhi[B_*N_*384], g_Xlo[B_*N_*384];
__device__ uint4 g_Bf[13*4096];
__device__ uint4 g_Pf[12*12288];          // proj fragments [l*3+p][wx][ks24][nt][lane]
__device__ float g_y012[B_*N_*3*CS_];
__device__ float g_y34[B_*2*CS_];
__device__ float g_Vrow[B_*N_*C_];
__device__ float g_Vcol[B_*N_*C_];
__device__ float g_Dd[B_*N_*C_];
__device__ float g_G[B_*C_];
__device__ float g_E[B_*C_];
__device__ float g_dg[B_*C_];
__device__ float g_tot[B_*C_];

__device__ __forceinline__ float lrelu(float x){ return x >= 0.f ? x : 0.01f*x; }
__device__ __forceinline__ uint32_t smem_u32(const void* p) {
    uint32_t a;
    asm("{ .reg .u64 t; cvta.to.shared.u64 t, %1; cvt.u32.u64 %0, t; }" : "=r"(a) : "l"(p));
    return a;
}
__device__ __forceinline__ void split2(float v, __nv_bfloat16& h, __nv_bfloat16& l) {
    h = __float2bfloat16(v);
    l = __float2bfloat16(v - __bfloat162float(h));
}
__device__ __forceinline__ uint32_t packbf(__nv_bfloat16 a, __nv_bfloat16 b) {
    __nv_bfloat162 p; p.x = a; p.y = b;
    return *(uint32_t*)&p;
}
__device__ __forceinline__ void ldmx4(uint32_t a, uint32_t& r0, uint32_t& r1, uint32_t& r2, uint32_t& r3) {
    asm volatile("ldmatrix.sync.aligned.m8n8.x4.shared.b16 {%0,%1,%2,%3}, [%4];"
                 : "=r"(r0), "=r"(r1), "=r"(r2), "=r"(r3) : "r"(a));
}
__device__ __forceinline__ void mma16816(float* c, const uint32_t* a, uint32_t b0, uint32_t b1) {
    asm volatile("mma.sync.aligned.m16n8k16.row.col.f32.bf16.bf16.f32 "
                 "{%0,%1,%2,%3}, {%4,%5,%6,%7}, {%8,%9}, {%0,%1,%2,%3};"
                 : "+f"(c[0]), "+f"(c[1]), "+f"(c[2]), "+f"(c[3])
                 : "r"(a[0]), "r"(a[1]), "r"(a[2]), "r"(a[3]), "r"(b0), "r"(b1));
}
#define CPA16(dst, src) asm volatile("cp.async.ca.shared.global [%0], [%1], 16;" :: "r"(dst), "l"(src))
#define CPCOMMIT() asm volatile("cp.async.commit_group;" ::: "memory")
#define CPWAIT1()  asm volatile("cp.async.wait_group 1;"  ::: "memory")
#define CPWAIT()   asm volatile("cp.async.wait_group 0;"  ::: "memory")

#define ALO2  34816
#define SM_G  69632
#define PROW  784          // bytes: (384+8) bf16 row stride in proj smem
#define ALOP  100352       // 128*784
#define SM_P  200704

// ---------------- one-time setup: Bf pack + proj fragment pack + eq1to2 prep ----------
__global__ void k_setup(const float* __restrict__ m0, const float* __restrict__ m1,
                        const float* __restrict__ m2, const float* __restrict__ m3,
                        const float* __restrict__ e0, const float* __restrict__ e1,
                        const float* __restrict__ e2, const float* __restrict__ e3,
                        const float* __restrict__ wfin,
                        const float* __restrict__ scalars, const int* __restrict__ nobj,
                        const float* __restrict__ w_in) {
    int blk = blockIdx.x, tid = threadIdx.x;
    if (blk < 52) {
        int mat = blk >> 2, quar = blk & 3;
        const float* W;
        if (mat < 4)       W = (mat==0)?m0:(mat==1)?m1:(mat==2)?m2:m3;
        else if (mat < 12) {
            int l = (mat-4)>>1, wh = (mat-4)&1;
            const float* E = (l==0)?e0:(l==1)?e1:(l==2)?e2:e3;
            W = E + wh*16384;
        } else W = wfin;
        uint4* dst = g_Bf + mat*4096;
        for (int e = quar*1024 + tid; e < quar*1024 + 1024; e += 256) {
            int lane = e&31, nt = (e>>5)&7, ks = (e>>8)&7, wx = e>>11;
            int n = wx*64 + nt*8 + (lane>>2);
            int k0 = ks*16 + (lane&3)*2;
            __nv_bfloat16 h00,l00,h01,l01,h10,l10,h11,l11;
            split2(W[k0*128+n],     h00, l00);
            split2(W[(k0+1)*128+n], h01, l01);
            split2(W[(k0+8)*128+n], h10, l10);
            split2(W[(k0+9)*128+n], h11, l11);
            uint4 o;
            o.x = packbf(h00,h01); o.y = packbf(h10,h11);
            o.z = packbf(l00,l01); o.w = packbf(l10,l11);
            dst[e] = o;
        }
    } else if (blk < 100) {
        // proj fragments: unit=(blk-52)/4 -> (l,p); quar=(blk-52)&3
        int idx = blk - 52;
        int unit = idx >> 2, quar = idx & 3;
        int l = unit / 3, p = unit % 3;
        const int tbl[3][3] = {{3,5,7},{4,6,8},{2,9,10}};
        const float* E = (l==0)?e0:(l==1)?e1:(l==2)?e2:e3;
        uint4* dst = g_Pf + (size_t)unit*12288;
        for (int e = quar*3072 + tid; e < quar*3072 + 3072; e += 256) {
            int wx = e / 6144, rem = e % 6144;
            int ks = rem >> 8, nt = (rem>>5)&7, lane = rem&31;
            int n = wx*64 + nt*8 + (lane>>2);
            int k0 = ks*16 + (lane&3)*2;
            __nv_bfloat16 hh[4], ll[4];
            #pragma unroll
            for (int q = 0; q < 4; q++) {
                int k = k0 + (q>>1)*8 + (q&1);
                int mat = tbl[p][k>>7], kk = k&127;
                split2(E[(mat*C_ + kk)*C_ + n], hh[q], ll[q]);
            }
            uint4 o;
            o.x = packbf(hh[0],hh[1]); o.y = packbf(hh[2],hh[3]);
            o.z = packbf(ll[0],ll[1]); o.w = packbf(ll[2],ll[3]);
            dst[e] = o;
        }
    } else {
        int b = blk - 100;
        __shared__ float xs[N_][S_];
        __shared__ float ssum[S_];
        int nb = nobj[b];
        for (int idx = tid; idx < N_*S_; idx += 256) {
            int n = idx/S_, s = idx%S_;
            xs[n][s] = (n < nb) ? scalars[(b*N_+n)*S_+s] : 0.f;
        }
        __syncthreads();
        if (tid < S_) {
            float a = 0.f;
            for (int n = 0; n < N_; n++) a += xs[n][tid];
            ssum[tid] = a / AVGF;
        }
        __syncthreads();
        for (int idx = tid; idx < N_*CS_; idx += 256) {
            int n = idx/CS_, c = idx%CS_;
            float a0=0, a1=0, a2=0;
            #pragma unroll
            for (int s = 0; s < S_; s++) {
                float xv = xs[n][s];
                a0 += xv*w_in[(0*S_+s)*CS_+c];
                a1 += xv*w_in[(1*S_+s)*CS_+c];
                a2 += xv*w_in[(2*S_+s)*CS_+c];
            }
            g_y012[((b*N_+n)*3+0)*CS_+c] = a0;
            g_y012[((b*N_+n)*3+1)*CS_+c] = a1;
            g_y012[((b*N_+n)*3+2)*CS_+c] = a2;
        }
        if (tid < 2*CS_) {
            int k = tid/CS_, c = tid%CS_;
            float a = 0.f;
            #pragma unroll
            for (int s = 0; s < S_; s++) a += ssum[s]*w_in[((3+k)*S_+s)*CS_+c];
            g_y34[(b*2+k)*CS_+c] = a;
        }
    }
}

// ---------------- GEMM helpers ----------------
struct GemmCtx {
    uint32_t sb;
    int tid, wid, lane, tile, b, i0, nb;
    int wy, wx, rb, nb0, lrow, lcolb, g, t2;
};
__device__ __forceinline__ void stage_src(const GemmCtx& X, const __nv_bfloat16* Ahi,
                                          const __nv_bfloat16* Alo, bool transp) {
    #pragma unroll
    for (int uu = 0; uu < 16; uu++) {
        int group = uu>>3, comp = (uu>>2)&1, sub = uu&3;
        int f = X.tid + 256*(comp*8 + group*4 + sub);
        int idx = f & 2047;
        int row = (idx>>3)&127, c8 = idx&7, c16 = group*8 + c8;
        const __nv_bfloat16* basep = comp ? Alo : Ahi;
        size_t goff;
        if (!transp) {
            goff = (size_t)X.tile*16384 + row*128 + c16*8;
        } else {
            int jj = row&63, hh = row>>6;
            goff = ((size_t)(X.b*32 + (jj>>1))*128 + (jj&1)*64 + X.i0 + hh)*128 + c16*8;
        }
        uint32_t dst = X.sb + comp*ALO2 + row*272 + c16*16;
        CPA16(dst, basep + goff);
        if (uu == 7) CPCOMMIT();
    }
    CPCOMMIT();
}
__device__ __forceinline__ void compute_pass(const GemmCtx& X, const uint4* Fw,
                                             float c[2][8][4], bool staged) {
    #pragma unroll
    for (int half = 0; half < 2; half++) {
        if (staged) { if (half == 0) CPWAIT1(); else CPWAIT(); __syncthreads(); }
        #pragma unroll
        for (int ks = half*4; ks < half*4+4; ks++) {
            uint32_t ah[2][4], al[2][4];
            #pragma unroll
            for (int mt = 0; mt < 2; mt++) {
                uint32_t adr = X.sb + (X.rb + mt*16 + X.lrow)*272 + ks*32 + X.lcolb;
                ldmx4(adr, ah[mt][0], ah[mt][1], ah[mt][2], ah[mt][3]);
                adr += ALO2;
                ldmx4(adr, al[mt][0], al[mt][1], al[mt][2], al[mt][3]);
            }
            uint4 f4 = Fw[(ks*8)*32 + X.lane];
            #pragma unroll
            for (int nt = 0; nt < 8; nt++) {
                uint4 cur = f4;
                if (nt < 7) f4 = Fw[(ks*8 + nt + 1)*32 + X.lane];
                #pragma unroll
                for (int mt = 0; mt < 2; mt++) {
                    mma16816(c[mt][nt], ah[mt], cur.x, cur.y);
                    mma16816(c[mt][nt], ah[mt], cur.z, cur.w);
                    mma16816(c[mt][nt], al[mt], cur.x, cur.y);
                }
            }
        }
    }
}
__device__ __forceinline__ void init_ctx(GemmCtx& X, unsigned char* sm) {
    X.sb = smem_u32(sm);
    X.tid = threadIdx.x; X.wid = X.tid>>5; X.lane = X.tid&31;
    X.tile = blockIdx.x; X.b = X.tile>>5; X.i0 = (X.tile&31)<<1;
    X.wy = X.wid&3; X.wx = X.wid>>2;
    X.rb = X.wy*32; X.nb0 = X.wx*64;
    X.lrow = (X.lane&7) + ((X.lane>>3)&1)*8;
    X.lcolb = ((X.lane>>4)&1)*16;
    X.g = X.lane>>2; X.t2 = (X.lane&3)*2;
}
#define ZEROC(c) { _Pragma("unroll") for (int mt=0;mt<2;mt++) _Pragma("unroll") for (int nt=0;nt<8;nt++) _Pragma("unroll") for (int q=0;q<4;q++) c[mt][nt][q]=0.f; }

__device__ __forceinline__ void epilogue_U(const GemmCtx& X, float c[2][8][4],
                                           const float* bias,
                                           __nv_bfloat16* OutHi, __nv_bfloat16* OutLo) {
    __nv_bfloat16* Hi = OutHi + (size_t)X.tile*16384;
    __nv_bfloat16* Lo = OutLo + (size_t)X.tile*16384;
    #pragma unroll
    for (int mt = 0; mt < 2; mt++)
        #pragma unroll
        for (int h = 0; h < 2; h++) {
            int row = X.rb + mt*16 + X.g + h*8;
            int i = X.i0 + (row>>6), j = row&63;
            float mask = (i < X.nb && j < X.nb) ? 1.f : 0.f;
            #pragma unroll
            for (int nt = 0; nt < 8; nt++) {
                int col = X.nb0 + nt*8 + X.t2;
                float vx = lrelu(c[mt][nt][h*2+0] + bias[col])   * mask;
                float vy = lrelu(c[mt][nt][h*2+1] + bias[col+1]) * mask;
                __nv_bfloat16 hx,lx,hy,ly;
                split2(vx, hx, lx); split2(vy, hy, ly);
                *(uint32_t*)(Hi + row*128 + col) = packbf(hx, hy);
                *(uint32_t*)(Lo + row*128 + col) = packbf(lx, ly);
            }
        }
}

// ---------------- mode-0 GEMM ----------------
__global__ void __launch_bounds__(256, 2) k_gemm0(const __nv_bfloat16* __restrict__ Ahi,
                                                  const __nv_bfloat16* __restrict__ Alo,
                                                  const uint4* __restrict__ F,
                                                  const float* __restrict__ bias,
                                                  const int* __restrict__ nobj,
                                                  __nv_bfloat16* __restrict__ OutHi,
                                                  __nv_bfloat16* __restrict__ OutLo) {
    extern __shared__ unsigned char sm[];
    GemmCtx X; init_ctx(X, sm);
    X.nb = nobj[X.b];
    if (X.i0 >= X.nb) return;
    float c[2][8][4]; ZEROC(c);
    stage_src(X, Ahi, Alo, false);
    compute_pass(X, F + X.wx*2048, c, true);
    epilogue_U(X, c, bias, OutHi, OutLo);
}

// ---------------- fused GEMM: Eq2to2 dual + combine -> T(smem) -> next GEMM ----------
__global__ void __launch_bounds__(256, 2) k_gemm2(const __nv_bfloat16* __restrict__ Uhi,
                                                  const __nv_bfloat16* __restrict__ Ulo,
                                                  const uint4* __restrict__ F0,
                                                  const uint4* __restrict__ F1,
                                                  const uint4* __restrict__ F2,
                                                  const float* __restrict__ bias2,
                                                  const int* __restrict__ nobj, int mode2,
                                                  __nv_bfloat16* __restrict__ OutHi,
                                                  __nv_bfloat16* __restrict__ OutLo) {
    extern __shared__ unsigned char sm[];
    GemmCtx X; init_ctx(X, sm);
    X.nb = nobj[X.b];
    if (X.i0 >= X.nb) return;
    float c[2][8][4]; ZEROC(c);
    stage_src(X, Uhi, Ulo, false);
    compute_pass(X, F0 + X.wx*2048, c, true);
    __syncthreads();
    stage_src(X, Uhi, Ulo, true);
    compute_pass(X, F1 + X.wx*2048, c, true);
    __syncthreads();
    #pragma unroll
    for (int mt = 0; mt < 2; mt++)
        #pragma unroll
        for (int h = 0; h < 2; h++) {
            int row = X.rb + mt*16 + X.g + h*8;
            int i = X.i0 + (row>>6), j = row&63;
            float mask = (i < X.nb && j < X.nb) ? 1.f : 0.f;
            bool diag = (i == j);
            const float* vr = g_Vrow + (X.b*64+i)*C_;
            const float* vc = g_Vcol + (X.b*64+j)*C_;
            const float* gg = g_G + X.b*C_;
            const float* dd = g_Dd + (X.b*64+i)*C_;
            const float* ee = g_E + X.b*C_;
            #pragma unroll
            for (int nt = 0; nt < 8; nt++) {
                int col = X.nb0 + nt*8 + X.t2;
                float vx = c[mt][nt][h*2+0] + vr[col]   + gg[col]   + vc[col];
                float vy = c[mt][nt][h*2+1] + vr[col+1] + gg[col+1] + vc[col+1];
                if (diag) { vx += dd[col] + ee[col]; vy += dd[col+1] + ee[col+1]; }
                vx = lrelu(vx) * mask;
                vy = lrelu(vy) * mask;
                __nv_bfloat16 hx,lx,hy,ly;
                split2(vx, hx, lx); split2(vy, hy, ly);
                *(uint32_t*)(sm + row*272 + col*2)        = packbf(hx, hy);
                *(uint32_t*)(sm + ALO2 + row*272 + col*2) = packbf(lx, ly);
            }
        }
    __syncthreads();
    ZEROC(c);
    compute_pass(X, F2 + X.wx*2048, c, false);
    if (mode2 == 0) {
        epilogue_U(X, c, bias2, OutHi, OutLo);
    } else {
        __syncthreads();
        float* Vs = (float*)sm;
        #pragma unroll
        for (int mt = 0; mt < 2; mt++)
            #pragma unroll
            for (int h = 0; h < 2; h++) {
                int row = X.rb + mt*16 + X.g + h*8;
                int i = X.i0 + (row>>6), j = row&63;
                float mask = (i < X.nb && j < X.nb) ? 1.f : 0.f;
                #pragma unroll
                for (int nt = 0; nt < 8; nt++) {
                    int col = X.nb0 + nt*8 + X.t2;
                    float2 v;
                    v.x = lrelu(c[mt][nt][h*2+0] + bias2[col])   * mask;
                    v.y = lrelu(c[mt][nt][h*2+1] + bias2[col+1]) * mask;
                    *(float2*)(Vs + row*132 + col) = v;
                }
            }
        __syncthreads();
        if (X.tid < 128) {
            float s = 0.f;
            #pragma unroll 8
            for (int r = 0; r < 128; r++) s += Vs[r*132 + X.tid];
            atomicAdd(&g_tot[X.b*C_ + X.tid], s);
            float dgv = Vs[X.i0*132 + X.tid] + Vs[(64 + X.i0 + 1)*132 + X.tid];
            atomicAdd(&g_dg[X.b*C_ + X.tid], dgv);
        }
    }
}

// ---------------- proj GEMM (fragment B, full-K cp.async A) + fused G/E --------------
__global__ void __launch_bounds__(256, 1) k_proj(const uint4* __restrict__ Pf,
                                                 const float* __restrict__ W,
                                                 const float* __restrict__ eqb,
                                                 const float* __restrict__ eqbd,
                                                 const int* __restrict__ nobj) {
    extern __shared__ unsigned char sm[];
    if (blockIdx.x >= 48) {
        int b = blockIdx.x - 48, d = threadIdx.x;
        float* tt = (float*)sm;
        float* tg = (float*)sm + 128;
        if (d < 128) {
            int nb = nobj[b];
            float t = 0.f, tr = 0.f;
            for (int i = 0; i < nb; i++) {
                size_t m = (size_t)(b*N_+i);
                t  += __bfloat162float(g_Xhi[m*384 + 128 + d]) + __bfloat162float(g_Xlo[m*384 + 128 + d]);
                tr += __bfloat162float(g_Xhi[m*384 + d])       + __bfloat162float(g_Xlo[m*384 + d]);
            }
            tt[d] = t / AVGF; tg[d] = tr / AVGF;
        }
        __syncthreads();
        if (d < 128) {
            float g = eqb[d], e = eqbd[d];
            for (int c = 0; c < C_; c++) {
                g += tt[c]*W[(11*C_+c)*C_+d] + tg[c]*W[(13*C_+c)*C_+d];
                e += tt[c]*W[(12*C_+c)*C_+d] + tg[c]*W[(14*C_+c)*C_+d];
            }
            g_G[b*C_+d] = g; g_E[b*C_+d] = e;
        }
        return;
    }
    uint32_t sb = smem_u32(sm);
    int tid = threadIdx.x, wid = tid>>5, lane = tid&31;
    int p = blockIdx.x >> 4, tile = blockIdx.x & 15;
    int wy = wid&3, wx = wid>>2;
    int rb = wy*32, nb0 = wx*64;
    float c[2][8][4]; ZEROC(c);
    int lrow = (lane&7) + ((lane>>3)&1)*8;
    int lcolb = ((lane>>4)&1)*16;
    // stage A: Xhi/Xlo rows [tile*128 .. +128), 384 cols, in 2 K-half commit groups
    #pragma unroll
    for (int uu = 0; uu < 48; uu++) {
        int khalf = uu / 24, v = uu % 24;
        int idx = tid + 256*v;               // 0..6143
        int comp = idx / 3072, rem = idx % 3072;
        int row = rem / 24, gr = rem % 24;   // k-granule within half
        int kg = khalf*24 + gr;
        const __nv_bfloat16* basep = comp ? g_Xlo : g_Xhi;
        size_t goff = (size_t)(tile*128 + row)*384 + kg*8;
        uint32_t dst = sb + comp*ALOP + row*PROW + kg*16;
        CPA16(dst, basep + goff);
        if (uu == 23) CPCOMMIT();
    }
    CPCOMMIT();
    const uint4* Fw = Pf + (size_t)p*12288 + wx*6144;
    #pragma unroll
    for (int half = 0; half < 2; half++) {
        if (half == 0) CPWAIT1(); else CPWAIT();
        __syncthreads();
        #pragma unroll
        for (int ks = half*12; ks < half*12+12; ks++) {
            uint32_t ah[2][4], al[2][4];
            #pragma unroll
            for (int mt = 0; mt < 2; mt++) {
                uint32_t adr = sb + (rb + mt*16 + lrow)*PROW + ks*32 + lcolb;
                ldmx4(adr, ah[mt][0], ah[mt][1], ah[mt][2], ah[mt][3]);
                adr += ALOP;
                ldmx4(adr, al[mt][0], al[mt][1], al[mt][2], al[mt][3]);
            }
            uint4 f4 = Fw[(ks*8)*32 + lane];
            #pragma unroll
            for (int nt = 0; nt < 8; nt++) {
                uint4 cur = f4;
                if (nt < 7) f4 = Fw[(ks*8 + nt + 1)*32 + lane];
                #pragma unroll
                for (int mt = 0; mt < 2; mt++) {
                    mma16816(c[mt][nt], ah[mt], cur.x, cur.y);
                    mma16816(c[mt][nt], ah[mt], cur.z, cur.w);
                    mma16816(c[mt][nt], al[mt], cur.x, cur.y);
                }
            }
        }
    }
    float* Out = (p==0) ? g_Vrow : (p==1) ? g_Vcol : g_Dd;
    int g = lane>>2, t2 = (lane&3)*2;
    #pragma unroll
    for (int mt = 0; mt < 2; mt++)
        #pragma unroll
        for (int h = 0; h < 2; h++) {
            int row = rb + mt*16 + g + h*8;
            int m = tile*128 + row;
            #pragma unroll
            for (int nt = 0; nt < 8; nt++) {
                int col = nb0 + nt*8 + t2;
                float2 v;
                v.x = c[mt][nt][h*2+0];
                v.y = c[mt][nt][h*2+1];
                *(float2*)(Out + (size_t)m*128 + col) = v;
            }
        }
}

// ---------------- initial T ----------------
__global__ void k_init(const float* __restrict__ momenta, const int* __restrict__ nobj,
                       const float* __restrict__ w_lin, const float* __restrict__ alpha,
                       const float* __restrict__ b_in) {
    int b = blockIdx.x / N_, i = blockIdx.x % N_;
    int nb = nobj[b];
    if (i >= nb) return;
    int tid = threadIdx.x;
    int c = tid & 127, jh = tid >> 7;
    __shared__ float pm[N_][4];
    __shared__ float dij[N_];
    __shared__ float y1s[N_][CS_];
    __shared__ float y0r[CS_], y2r[CS_], y3s[CS_], y4s[CS_];
    if (tid < 256) pm[tid>>2][tid&3] = momenta[(b*N_)*4 + tid];
    for (int idx = tid; idx < N_*CS_; idx += 256) {
        int n = idx/CS_, cs = idx%CS_;
        y1s[n][cs] = g_y012[((b*N_+n)*3+1)*CS_+cs];
    }
    if (tid < CS_) {
        y0r[tid] = g_y012[((b*N_+i)*3+0)*CS_+tid];
        y2r[tid] = g_y012[((b*N_+i)*3+2)*CS_+tid];
    } else if (tid < 2*CS_) {
        y3s[tid-CS_] = g_y34[(b*2+0)*CS_+tid-CS_];
    } else if (tid < 3*CS_) {
        y4s[tid-2*CS_] = g_y34[(b*2+1)*CS_+tid-2*CS_];
    }
    __syncthreads();
    if (tid < N_)
        dij[tid] = pm[i][0]*pm[tid][0] - pm[i][1]*pm[tid][1]
                 - pm[i][2]*pm[tid][2] - pm[i][3]*pm[tid][3];
    __syncthreads();
    float base = 0.f, wl = 0.f, al = 0.f;
    if (c < CS_) base = y0r[c] + y3s[c] + b_in[c];
    else { wl = w_lin[c-CS_]; al = alpha[c-CS_]; }
    size_t rowbase = ((size_t)(b*32 + (i>>1))*128 + (i&1)*64)*128;
    for (int j = jh; j < N_; j += 2) {
        float mask = (j < nb) ? 1.f : 0.f;
        float v;
        if (c < CS_) {
            v = base + y1s[j][c];
            if (j == i) v += y2r[c] + y4s[c];
            v = lrelu(v) * mask;
        } else {
            float r = dij[j] * wl;
            v = al * copysignf(log1pf(fabsf(r)), r) * mask;
        }
        __nv_bfloat16 h, l;
        split2(v, h, l);
        g_Ahi[rowbase + j*128 + c] = h;
        g_Alo[rowbase + j*128 + c] = l;
    }
}

// ---------------- reductions: U -> X (bf16 hi/lo out) ----------------
__global__ void k_r1(const __nv_bfloat16* __restrict__ Uhi,
                     const __nv_bfloat16* __restrict__ Ulo,
                     const int* __restrict__ nobj) {
    int b = blockIdx.x >> 6, i = blockIdx.x & 63;
    if (i >= nobj[b]) return;
    int t = threadIdx.x;
    int g = t & 15, jg = t >> 4;
    __shared__ float redR[16][128], redC[16][128];
    float aR[8] = {0,0,0,0,0,0,0,0}, aC[8] = {0,0,0,0,0,0,0,0};
    #pragma unroll
    for (int jj = 0; jj < 4; jj++) {
        int j = jg*4 + jj;
        {
            size_t off = ((size_t)(b*32 + (i>>1))*128 + (i&1)*64 + j)*128 + g*8;
            uint4 h4 = *(const uint4*)(Uhi + off);
            uint4 l4 = *(const uint4*)(Ulo + off);
            const __nv_bfloat16 *hp = (const __nv_bfloat16*)&h4, *lp = (const __nv_bfloat16*)&l4;
            #pragma unroll
            for (int q = 0; q < 8; q++) aR[q] += __bfloat162float(hp[q]) + __bfloat162float(lp[q]);
        }
        {
            size_t off = ((size_t)(b*32 + (j>>1))*128 + (j&1)*64 + i)*128 + g*8;
            uint4 h4 = *(const uint4*)(Uhi + off);
            uint4 l4 = *(const uint4*)(Ulo + off);
            const __nv_bfloat16 *hp = (const __nv_bfloat16*)&h4, *lp = (const __nv_bfloat16*)&l4;
            #pragma unroll
            for (int q = 0; q < 8; q++) aC[q] += __bfloat162float(hp[q]) + __bfloat162float(lp[q]);
        }
    }
    #pragma unroll
    for (int q = 0; q < 8; q++) { redR[jg][g*8+q] = aR[q]; redC[jg][g*8+q] = aC[q]; }
    __syncthreads();
    size_t m = (size_t)(b*N_+i);
    if (t < 128) {
        float s = 0.f;
        #pragma unroll
        for (int r = 0; r < 16; r++) s += redR[r][t];
        __nv_bfloat16 h, l; split2(s / AVGF, h, l);
        g_Xhi[m*384 + 128 + t] = h; g_Xlo[m*384 + 128 + t] = l;
    } else {
        int d = t - 128;
        float s = 0.f;
        #pragma unroll
        for (int r = 0; r < 16; r++) s += redC[r][d];
        __nv_bfloat16 h, l; split2(s / AVGF, h, l);
        g_Xhi[m*384 + 256 + d] = h; g_Xlo[m*384 + 256 + d] = l;
    }
    if (t < 16) {
        size_t off = ((size_t)(b*32 + (i>>1))*128 + (i&1)*64 + i)*128 + t*8;
        uint4 h4 = *(const uint4*)(Uhi + off);
        uint4 l4 = *(const uint4*)(Ulo + off);
        const __nv_bfloat16 *hp = (const __nv_bfloat16*)&h4, *lp = (const __nv_bfloat16*)&l4;
        #pragma unroll
        for (int q = 0; q < 8; q++) {
            __nv_bfloat16 h, l;
            split2(__bfloat162float(hp[q]) + __bfloat162float(lp[q]), h, l);
            g_Xhi[m*384 + t*8 + q] = h; g_Xlo[m*384 + t*8 + q] = l;
        }
    }
}

// ---------------- output head (resets accumulators) ----------------
__global__ void k_out(const float* __restrict__ w20, const float* __restrict__ b20,
                      const float* __restrict__ wmlp, const float* __restrict__ bmlp,
                      float* __restrict__ out) {
    int b = blockIdx.x, d = threadIdx.x;
    __shared__ float a0[C_], a1[C_], act[C_];
    a0[d] = lrelu(g_dg[b*C_+d] / AVGF);
    a1[d] = lrelu(g_tot[b*C_+d] / (AVGF*AVGF));
    g_dg[b*C_+d] = 0.f;
    g_tot[b*C_+d] = 0.f;
    __syncthreads();
    float a = b20[d];
    for (int c = 0; c < C_; c++) a += a0[c]*w20[c*C_+d] + a1[c]*w20[(C_+c)*C_+d];
    act[d] = a;
    __syncthreads();
    if (d < 2) {
        float o = bmlp[d];
        for (int k = 0; k < C_; k++) o += act[k]*wmlp[k*2+d];
        out[b*2+d] = o;
    }
}

// ---------------- host ----------------
extern "C" void kernel_launch(void* const* d_in, const int* in_sizes, int n_in,
                              void* d_out, int out_size) {
    const float *momenta=0, *scalars=0, *w_lin=0, *alpha=0, *w_in=0, *b_in=0;
    const int* nobj=0;
    const float *msgw[4], *msgb[4], *eqw[4], *eqb[4], *eqbd[4];
    const float *wm0=0, *bm0=0, *w20=0, *b20=0, *wmlp=0, *bmlp=0;

    if (n_in >= 33 && in_sizes[0] == 8192) {
        momenta=(const float*)d_in[0]; scalars=(const float*)d_in[1]; nobj=(const int*)d_in[2];
        w_lin=(const float*)d_in[3]; alpha=(const float*)d_in[4]; w_in=(const float*)d_in[5];
        b_in=(const float*)d_in[6];
        for (int l = 0; l < 4; l++) {
            msgw[l]=(const float*)d_in[7+l];  msgb[l]=(const float*)d_in[11+l];
            eqw[l] =(const float*)d_in[15+l]; eqb[l] =(const float*)d_in[19+l];
            eqbd[l]=(const float*)d_in[23+l];
        }
        wm0=(const float*)d_in[27]; bm0=(const float*)d_in[28]; w20=(const float*)d_in[29];
        b20=(const float*)d_in[30]; wmlp=(const float*)d_in[31]; bmlp=(const float*)d_in[32];
    } else if (n_in >= 33) {
        alpha=(const float*)d_in[0]; b20=(const float*)d_in[1]; b_in=(const float*)d_in[2];
        bm0=(const float*)d_in[3]; bmlp=(const float*)d_in[4];
        for (int l = 0; l < 4; l++) {
            eqb[l] =(const float*)d_in[5+l];  eqbd[l]=(const float*)d_in[9+l];
            eqw[l] =(const float*)d_in[13+l]; msgb[l]=(const float*)d_in[18+l];
            msgw[l]=(const float*)d_in[22+l];
        }
        momenta=(const float*)d_in[17]; nobj=(const int*)d_in[26]; scalars=(const float*)d_in[27];
        w20=(const float*)d_in[28]; w_in=(const float*)d_in[29]; w_lin=(const float*)d_in[30];
        wm0=(const float*)d_in[31]; wmlp=(const float*)d_in[32];
    } else {
        momenta=(const float*)d_in[0]; scalars=(const float*)d_in[1]; nobj=(const int*)d_in[2];
        w_lin=(const float*)d_in[3]; alpha=(const float*)d_in[4]; w_in=(const float*)d_in[5];
        b_in=(const float*)d_in[6];
        for (int l = 0; l < 4; l++) {
            msgw[l]=(const float*)d_in[7]+(size_t)l*C_*C_;     msgb[l]=(const float*)d_in[8]+(size_t)l*C_;
            eqw[l] =(const float*)d_in[9]+(size_t)l*15*C_*C_;  eqb[l] =(const float*)d_in[10]+(size_t)l*C_;
            eqbd[l]=(const float*)d_in[11]+(size_t)l*C_;
        }
        wm0=(const float*)d_in[12]; bm0=(const float*)d_in[13]; w20=(const float*)d_in[14];
        b20=(const float*)d_in[15]; wmlp=(const float*)d_in[16]; bmlp=(const float*)d_in[17];
    }

    cudaFuncSetAttribute(k_gemm0, cudaFuncAttributeMaxDynamicSharedMemorySize, SM_G);
    cudaFuncSetAttribute(k_gemm2, cudaFuncAttributeMaxDynamicSharedMemorySize, SM_G);
    cudaFuncSetAttribute(k_proj,  cudaFuncAttributeMaxDynamicSharedMemorySize, SM_P);

    __nv_bfloat16 *Ahi=0, *Alo=0, *Bhi=0, *Blo=0;
    uint4 *Bf=0, *Pf=0;
    cudaGetSymbolAddress((void**)&Ahi, g_Ahi);
    cudaGetSymbolAddress((void**)&Alo, g_Alo);
    cudaGetSymbolAddress((void**)&Bhi, g_Bhi);
    cudaGetSymbolAddress((void**)&Blo, g_Blo);
    cudaGetSymbolAddress((void**)&Bf,  g_Bf);
    cudaGetSymbolAddress((void**)&Pf,  g_Pf);

    k_setup<<<132, 256>>>(msgw[0], msgw[1], msgw[2], msgw[3],
                          eqw[0], eqw[1], eqw[2], eqw[3], wm0,
                          scalars, nobj, w_in);
    k_init<<<B_*N_, 256>>>(momenta, nobj, w_lin, alpha, b_in);

    k_gemm0<<<TILES, 256, SM_G>>>(Ahi, Alo, Bf + 0*4096, msgb[0], nobj, Bhi, Blo);

    __nv_bfloat16 *curHi = Bhi, *curLo = Blo, *nxtHi = Ahi, *nxtLo = Alo;
    for (int l = 0; l < 4; l++) {
        k_r1<<<B_*N_, 256>>>(curHi, curLo, nobj);
        k_proj<<<80, 256, SM_P>>>(Pf + (size_t)(l*3)*12288,
                                  eqw[l], eqb[l], eqbd[l], nobj);
        if (l < 3) {
            k_gemm2<<<TILES, 256, SM_G>>>(curHi, curLo,
                                          Bf + (4 + l*2)*4096, Bf + (5 + l*2)*4096,
                                          Bf + (l+1)*4096, msgb[l+1], nobj, 0,
                                          nxtHi, nxtLo);
            __nv_bfloat16* th = curHi; curHi = nxtHi; nxtHi = th;
            __nv_bfloat16* tl = curLo; curLo = nxtLo; nxtLo = tl;
        } else {
            k_gemm2<<<TILES, 256, SM_G>>>(curHi, curLo,
                                          Bf + (4 + l*2)*4096, Bf + (5 + l*2)*4096,
                                          Bf + 12*4096, bm0, nobj, 3,
                                          (__nv_bfloat16*)0, (__nv_bfloat16*)0);
        }
    }

    k_out<<<B_, 128>>>(w20, b20, wmlp, bmlp, (float*)d_out);
}

// round 15
// speedup vs baseline: 1.1334x; 1.0400x over previous
#include <cuda_runtime.h>
#include <cuda_bf16.h>
#include <math.h>
#include <stdint.h>

#define B_  32
#define N_  64
#define S_  9
#define C_  128
#define CS_ 32
#define AVGF 49.0f
#define TILES (B_*32)

// ---------------- device scratch ----------------
__device__ __nv_bfloat16 g_Ahi[TILES*16384], g_Alo[TILES*16384];
__device__ __nv_bfloat16 g_Bhi[TILES*16384], g_Blo[TILES*16384];
__device__ __nv_bfloat16 g_Xhi[B_*N_*384], g_Xlo[B_*N_*384];
__device__ uint4 g_Bf[13*4096];
__device__ uint4 g_Pf[12*12288];
__device__ float g_y012[B_*N_*3*CS_];
__device__ float g_y34[B_*2*CS_];
__device__ float g_Vrow[B_*N_*C_];
__device__ float g_Vcol[B_*N_*C_];
__device__ float g_Dd[B_*N_*C_];
__device__ float g_G[B_*C_];
__device__ float g_E[B_*C_];
__device__ float g_dg[B_*C_];
__device__ float g_tot[B_*C_];

__device__ __forceinline__ float lrelu(float x){ return x >= 0.f ? x : 0.01f*x; }
__device__ __forceinline__ uint32_t smem_u32(const void* p) {
    uint32_t a;
    asm("{ .reg .u64 t; cvta.to.shared.u64 t, %1; cvt.u32.u64 %0, t; }" : "=r"(a) : "l"(p));
    return a;
}
__device__ __forceinline__ void split2(float v, __nv_bfloat16& h, __nv_bfloat16& l) {
    h = __float2bfloat16(v);
    l = __float2bfloat16(v - __bfloat162float(h));
}
__device__ __forceinline__ uint32_t packbf(__nv_bfloat16 a, __nv_bfloat16 b) {
    __nv_bfloat162 p; p.x = a; p.y = b;
    return *(uint32_t*)&p;
}
__device__ __forceinline__ void ldmx4(uint32_t a, uint32_t& r0, uint32_t& r1, uint32_t& r2, uint32_t& r3) {
    asm volatile("ldmatrix.sync.aligned.m8n8.x4.shared.b16 {%0,%1,%2,%3}, [%4];"
                 : "=r"(r0), "=r"(r1), "=r"(r2), "=r"(r3) : "r"(a));
}
__device__ __forceinline__ void mma16816(float* c, const uint32_t* a, uint32_t b0, uint32_t b1) {
    asm volatile("mma.sync.aligned.m16n8k16.row.col.f32.bf16.bf16.f32 "
                 "{%0,%1,%2,%3}, {%4,%5,%6,%7}, {%8,%9}, {%0,%1,%2,%3};"
                 : "+f"(c[0]), "+f"(c[1]), "+f"(c[2]), "+f"(c[3])
                 : "r"(a[0]), "r"(a[1]), "r"(a[2]), "r"(a[3]), "r"(b0), "r"(b1));
}
#define CPA16(dst, src) asm volatile("cp.async.ca.shared.global [%0], [%1], 16;" :: "r"(dst), "l"(src))
#define CPCOMMIT() asm volatile("cp.async.commit_group;" ::: "memory")
#define CPWAIT1()  asm volatile("cp.async.wait_group 1;"  ::: "memory")
#define CPWAIT()   asm volatile("cp.async.wait_group 0;"  ::: "memory")

#define ALO2  34816
#define SM_G  69632
#define PROW  784
#define ALOP  100352
#define SM_P  200704

// ---------------- one-time setup ----------------
__global__ void k_setup(const float* __restrict__ m0, const float* __restrict__ m1,
                        const float* __restrict__ m2, const float* __restrict__ m3,
                        const float* __restrict__ e0, const float* __restrict__ e1,
                        const float* __restrict__ e2, const float* __restrict__ e3,
                        const float* __restrict__ wfin,
                        const float* __restrict__ scalars, const int* __restrict__ nobj,
                        const float* __restrict__ w_in) {
    int blk = blockIdx.x, tid = threadIdx.x;
    if (blk < 52) {
        int mat = blk >> 2, quar = blk & 3;
        const float* W;
        if (mat < 4)       W = (mat==0)?m0:(mat==1)?m1:(mat==2)?m2:m3;
        else if (mat < 12) {
            int l = (mat-4)>>1, wh = (mat-4)&1;
            const float* E = (l==0)?e0:(l==1)?e1:(l==2)?e2:e3;
            W = E + wh*16384;
        } else W = wfin;
        uint4* dst = g_Bf + mat*4096;
        for (int e = quar*1024 + tid; e < quar*1024 + 1024; e += 256) {
            int lane = e&31, nt = (e>>5)&7, ks = (e>>8)&7, wx = e>>11;
            int n = wx*64 + nt*8 + (lane>>2);
            int k0 = ks*16 + (lane&3)*2;
            __nv_bfloat16 h00,l00,h01,l01,h10,l10,h11,l11;
            split2(W[k0*128+n],     h00, l00);
            split2(W[(k0+1)*128+n], h01, l01);
            split2(W[(k0+8)*128+n], h10, l10);
            split2(W[(k0+9)*128+n], h11, l11);
            uint4 o;
            o.x = packbf(h00,h01); o.y = packbf(h10,h11);
            o.z = packbf(l00,l01); o.w = packbf(l10,l11);
            dst[e] = o;
        }
    } else if (blk < 100) {
        int idx = blk - 52;
        int unit = idx >> 2, quar = idx & 3;
        int l = unit / 3, p = unit % 3;
        const int tbl[3][3] = {{3,5,7},{4,6,8},{2,9,10}};
        const float* E = (l==0)?e0:(l==1)?e1:(l==2)?e2:e3;
        uint4* dst = g_Pf + (size_t)unit*12288;
        for (int e = quar*3072 + tid; e < quar*3072 + 3072; e += 256) {
            int wx = e / 6144, rem = e % 6144;
            int ks = rem >> 8, nt = (rem>>5)&7, lane = rem&31;
            int n = wx*64 + nt*8 + (lane>>2);
            int k0 = ks*16 + (lane&3)*2;
            __nv_bfloat16 hh[4], ll[4];
            #pragma unroll
            for (int q = 0; q < 4; q++) {
                int k = k0 + (q>>1)*8 + (q&1);
                int mat = tbl[p][k>>7], kk = k&127;
                split2(E[(mat*C_ + kk)*C_ + n], hh[q], ll[q]);
            }
            uint4 o;
            o.x = packbf(hh[0],hh[1]); o.y = packbf(hh[2],hh[3]);
            o.z = packbf(ll[0],ll[1]); o.w = packbf(ll[2],ll[3]);
            dst[e] = o;
        }
    } else {
        int b = blk - 100;
        __shared__ float xs[N_][S_];
        __shared__ float ssum[S_];
        int nb = nobj[b];
        for (int idx = tid; idx < N_*S_; idx += 256) {
            int n = idx/S_, s = idx%S_;
            xs[n][s] = (n < nb) ? scalars[(b*N_+n)*S_+s] : 0.f;
        }
        __syncthreads();
        if (tid < S_) {
            float a = 0.f;
            for (int n = 0; n < N_; n++) a += xs[n][tid];
            ssum[tid] = a / AVGF;
        }
        __syncthreads();
        for (int idx = tid; idx < N_*CS_; idx += 256) {
            int n = idx/CS_, c = idx%CS_;
            float a0=0, a1=0, a2=0;
            #pragma unroll
            for (int s = 0; s < S_; s++) {
                float xv = xs[n][s];
                a0 += xv*w_in[(0*S_+s)*CS_+c];
                a1 += xv*w_in[(1*S_+s)*CS_+c];
                a2 += xv*w_in[(2*S_+s)*CS_+c];
            }
            g_y012[((b*N_+n)*3+0)*CS_+c] = a0;
            g_y012[((b*N_+n)*3+1)*CS_+c] = a1;
            g_y012[((b*N_+n)*3+2)*CS_+c] = a2;
        }
        if (tid < 2*CS_) {
            int k = tid/CS_, c = tid%CS_;
            float a = 0.f;
            #pragma unroll
            for (int s = 0; s < S_; s++) a += ssum[s]*w_in[((3+k)*S_+s)*CS_+c];
            g_y34[(b*2+k)*CS_+c] = a;
        }
    }
}

// ---------------- GEMM helpers ----------------
struct GemmCtx {
    uint32_t sb;
    int tid, wid, lane, tile, b, i0, nb;
    int wy, wx, rb, nb0, lrow, lcolb, g, t2;
};
__device__ __forceinline__ void stage_src(const GemmCtx& X, const __nv_bfloat16* Ahi,
                                          const __nv_bfloat16* Alo, bool transp) {
    #pragma unroll
    for (int uu = 0; uu < 16; uu++) {
        int group = uu>>3, comp = (uu>>2)&1, sub = uu&3;
        int f = X.tid + 256*(comp*8 + group*4 + sub);
        int idx = f & 2047;
        int row = (idx>>3)&127, c8 = idx&7, c16 = group*8 + c8;
        const __nv_bfloat16* basep = comp ? Alo : Ahi;
        size_t goff;
        if (!transp) {
            goff = (size_t)X.tile*16384 + row*128 + c16*8;
        } else {
            int jj = row&63, hh = row>>6;
            goff = ((size_t)(X.b*32 + (jj>>1))*128 + (jj&1)*64 + X.i0 + hh)*128 + c16*8;
        }
        uint32_t dst = X.sb + comp*ALO2 + row*272 + c16*16;
        CPA16(dst, basep + goff);
        if (uu == 7) CPCOMMIT();
    }
    CPCOMMIT();
}
__device__ __forceinline__ void compute_pass(const GemmCtx& X, const uint4* Fw,
                                             float c[2][8][4], bool staged) {
    #pragma unroll
    for (int half = 0; half < 2; half++) {
        if (staged) { if (half == 0) CPWAIT1(); else CPWAIT(); __syncthreads(); }
        #pragma unroll
        for (int ks = half*4; ks < half*4+4; ks++) {
            uint32_t ah[2][4], al[2][4];
            #pragma unroll
            for (int mt = 0; mt < 2; mt++) {
                uint32_t adr = X.sb + (X.rb + mt*16 + X.lrow)*272 + ks*32 + X.lcolb;
                ldmx4(adr, ah[mt][0], ah[mt][1], ah[mt][2], ah[mt][3]);
                adr += ALO2;
                ldmx4(adr, al[mt][0], al[mt][1], al[mt][2], al[mt][3]);
            }
            uint4 f4 = Fw[(ks*8)*32 + X.lane];
            #pragma unroll
            for (int nt = 0; nt < 8; nt++) {
                uint4 cur = f4;
                if (nt < 7) f4 = Fw[(ks*8 + nt + 1)*32 + X.lane];
                #pragma unroll
                for (int mt = 0; mt < 2; mt++) {
                    mma16816(c[mt][nt], ah[mt], cur.x, cur.y);
                    mma16816(c[mt][nt], ah[mt], cur.z, cur.w);
                    mma16816(c[mt][nt], al[mt], cur.x, cur.y);
                }
            }
        }
    }
}
__device__ __forceinline__ void init_ctx(GemmCtx& X, unsigned char* sm) {
    X.sb = smem_u32(sm);
    X.tid = threadIdx.x; X.wid = X.tid>>5; X.lane = X.tid&31;
    X.tile = blockIdx.x; X.b = X.tile>>5; X.i0 = (X.tile&31)<<1;
    X.wy = X.wid&3; X.wx = X.wid>>2;
    X.rb = X.wy*32; X.nb0 = X.wx*64;
    X.lrow = (X.lane&7) + ((X.lane>>3)&1)*8;
    X.lcolb = ((X.lane>>4)&1)*16;
    X.g = X.lane>>2; X.t2 = (X.lane&3)*2;
}
#define ZEROC(c) { _Pragma("unroll") for (int mt=0;mt<2;mt++) _Pragma("unroll") for (int nt=0;nt<8;nt++) _Pragma("unroll") for (int q=0;q<4;q++) c[mt][nt][q]=0.f; }

// epilogue: write U (bf16 hi/lo) + rvec/dvec into X (atomic-free; tile-local)
__device__ __forceinline__ void epilogue_UX(const GemmCtx& X, float c[2][8][4],
                                            const float* bias,
                                            __nv_bfloat16* OutHi, __nv_bfloat16* OutLo,
                                            unsigned char* sm) {
    __syncthreads();
    float* Vs = (float*)sm;   // [128][132]
    __nv_bfloat16* Hi = OutHi + (size_t)X.tile*16384;
    __nv_bfloat16* Lo = OutLo + (size_t)X.tile*16384;
    #pragma unroll
    for (int mt = 0; mt < 2; mt++)
        #pragma unroll
        for (int h = 0; h < 2; h++) {
            int row = X.rb + mt*16 + X.g + h*8;
            int i = X.i0 + (row>>6), j = row&63;
            float mask = (i < X.nb && j < X.nb) ? 1.f : 0.f;
            #pragma unroll
            for (int nt = 0; nt < 8; nt++) {
                int col = X.nb0 + nt*8 + X.t2;
                float vx = lrelu(c[mt][nt][h*2+0] + bias[col])   * mask;
                float vy = lrelu(c[mt][nt][h*2+1] + bias[col+1]) * mask;
                __nv_bfloat16 hx,lx,hy,ly;
                split2(vx, hx, lx); split2(vy, hy, ly);
                *(uint32_t*)(Hi + row*128 + col) = packbf(hx, hy);
                *(uint32_t*)(Lo + row*128 + col) = packbf(lx, ly);
                float2 v; v.x = vx; v.y = vy;
                *(float2*)(Vs + row*132 + col) = v;
            }
        }
    __syncthreads();
    int t = X.tid;
    int half = t >> 7, cc = t & 127;
    float s = 0.f;
    #pragma unroll 8
    for (int r = 0; r < 64; r++) s += Vs[(half*64 + r)*132 + cc];
    size_t m = (size_t)(X.b*64 + X.i0 + half);
    __nv_bfloat16 h, l;
    split2(s / AVGF, h, l);
    g_Xhi[m*384 + 128 + cc] = h; g_Xlo[m*384 + 128 + cc] = l;
    split2(Vs[(half*64 + X.i0 + half)*132 + cc], h, l);
    g_Xhi[m*384 + cc] = h; g_Xlo[m*384 + cc] = l;
}

// ---------------- mode-0 GEMM ----------------
__global__ void __launch_bounds__(256, 2) k_gemm0(const __nv_bfloat16* __restrict__ Ahi,
                                                  const __nv_bfloat16* __restrict__ Alo,
                                                  const uint4* __restrict__ F,
                                                  const float* __restrict__ bias,
                                                  const int* __restrict__ nobj,
                                                  __nv_bfloat16* __restrict__ OutHi,
                                                  __nv_bfloat16* __restrict__ OutLo) {
    extern __shared__ unsigned char sm[];
    GemmCtx X; init_ctx(X, sm);
    X.nb = nobj[X.b];
    if (X.i0 >= X.nb) return;
    float c[2][8][4]; ZEROC(c);
    stage_src(X, Ahi, Alo, false);
    compute_pass(X, F + X.wx*2048, c, true);
    epilogue_UX(X, c, bias, OutHi, OutLo, sm);
}

// ---------------- fused GEMM: Eq2to2 dual + combine -> T(smem) -> next GEMM ----------
__global__ void __launch_bounds__(256, 2) k_gemm2(const __nv_bfloat16* __restrict__ Uhi,
                                                  const __nv_bfloat16* __restrict__ Ulo,
                                                  const uint4* __restrict__ F0,
                                                  const uint4* __restrict__ F1,
                                                  const uint4* __restrict__ F2,
                                                  const float* __restrict__ bias2,
                                                  const int* __restrict__ nobj, int mode2,
                                                  __nv_bfloat16* __restrict__ OutHi,
                                                  __nv_bfloat16* __restrict__ OutLo) {
    extern __shared__ unsigned char sm[];
    GemmCtx X; init_ctx(X, sm);
    X.nb = nobj[X.b];
    if (X.i0 >= X.nb) return;
    float c[2][8][4]; ZEROC(c);
    stage_src(X, Uhi, Ulo, false);
    compute_pass(X, F0 + X.wx*2048, c, true);
    __syncthreads();
    stage_src(X, Uhi, Ulo, true);
    compute_pass(X, F1 + X.wx*2048, c, true);
    __syncthreads();
    #pragma unroll
    for (int mt = 0; mt < 2; mt++)
        #pragma unroll
        for (int h = 0; h < 2; h++) {
            int row = X.rb + mt*16 + X.g + h*8;
            int i = X.i0 + (row>>6), j = row&63;
            float mask = (i < X.nb && j < X.nb) ? 1.f : 0.f;
            bool diag = (i == j);
            const float* vr = g_Vrow + (X.b*64+i)*C_;
            const float* vc = g_Vcol + (X.b*64+j)*C_;
            const float* gg = g_G + X.b*C_;
            const float* dd = g_Dd + (X.b*64+i)*C_;
            const float* ee = g_E + X.b*C_;
            #pragma unroll
            for (int nt = 0; nt < 8; nt++) {
                int col = X.nb0 + nt*8 + X.t2;
                float vx = c[mt][nt][h*2+0] + vr[col]   + gg[col]   + vc[col];
                float vy = c[mt][nt][h*2+1] + vr[col+1] + gg[col+1] + vc[col+1];
                if (diag) { vx += dd[col] + ee[col]; vy += dd[col+1] + ee[col+1]; }
                vx = lrelu(vx) * mask;
                vy = lrelu(vy) * mask;
                __nv_bfloat16 hx,lx,hy,ly;
                split2(vx, hx, lx); split2(vy, hy, ly);
                *(uint32_t*)(sm + row*272 + col*2)        = packbf(hx, hy);
                *(uint32_t*)(sm + ALO2 + row*272 + col*2) = packbf(lx, ly);
            }
        }
    __syncthreads();
    ZEROC(c);
    compute_pass(X, F2 + X.wx*2048, c, false);
    if (mode2 == 0) {
        epilogue_UX(X, c, bias2, OutHi, OutLo, sm);
    } else {
        __syncthreads();
        float* Vs = (float*)sm;
        #pragma unroll
        for (int mt = 0; mt < 2; mt++)
            #pragma unroll
            for (int h = 0; h < 2; h++) {
                int row = X.rb + mt*16 + X.g + h*8;
                int i = X.i0 + (row>>6), j = row&63;
                float mask = (i < X.nb && j < X.nb) ? 1.f : 0.f;
                #pragma unroll
                for (int nt = 0; nt < 8; nt++) {
                    int col = X.nb0 + nt*8 + X.t2;
                    float2 v;
                    v.x = lrelu(c[mt][nt][h*2+0] + bias2[col])   * mask;
                    v.y = lrelu(c[mt][nt][h*2+1] + bias2[col+1]) * mask;
                    *(float2*)(Vs + row*132 + col) = v;
                }
            }
        __syncthreads();
        if (X.tid < 128) {
            float s = 0.f;
            #pragma unroll 8
            for (int r = 0; r < 128; r++) s += Vs[r*132 + X.tid];
            atomicAdd(&g_tot[X.b*C_ + X.tid], s);
            float dgv = Vs[X.i0*132 + X.tid] + Vs[(64 + X.i0 + 1)*132 + X.tid];
            atomicAdd(&g_dg[X.b*C_ + X.tid], dgv);
        }
    }
}

// ---------------- proj GEMM (fragment B, full-K cp.async A) + fused G/E --------------
__global__ void __launch_bounds__(256, 1) k_proj(const uint4* __restrict__ Pf,
                                                 const float* __restrict__ W,
                                                 const float* __restrict__ eqb,
                                                 const float* __restrict__ eqbd,
                                                 const int* __restrict__ nobj) {
    extern __shared__ unsigned char sm[];
    if (blockIdx.x >= 48) {
        int b = blockIdx.x - 48, d = threadIdx.x;
        float* tt = (float*)sm;
        float* tg = (float*)sm + 128;
        if (d < 128) {
            int nb = nobj[b];
            float t = 0.f, tr = 0.f;
            for (int i = 0; i < nb; i++) {
                size_t m = (size_t)(b*N_+i);
                t  += __bfloat162float(g_Xhi[m*384 + 128 + d]) + __bfloat162float(g_Xlo[m*384 + 128 + d]);
                tr += __bfloat162float(g_Xhi[m*384 + d])       + __bfloat162float(g_Xlo[m*384 + d]);
            }
            tt[d] = t / AVGF; tg[d] = tr / AVGF;
        }
        __syncthreads();
        if (d < 128) {
            float g = eqb[d], e = eqbd[d];
            for (int c = 0; c < C_; c++) {
                g += tt[c]*W[(11*C_+c)*C_+d] + tg[c]*W[(13*C_+c)*C_+d];
                e += tt[c]*W[(12*C_+c)*C_+d] + tg[c]*W[(14*C_+c)*C_+d];
            }
            g_G[b*C_+d] = g; g_E[b*C_+d] = e;
        }
        return;
    }
    uint32_t sb = smem_u32(sm);
    int tid = threadIdx.x, wid = tid>>5, lane = tid&31;
    int p = blockIdx.x >> 4, tile = blockIdx.x & 15;
    int wy = wid&3, wx = wid>>2;
    int rb = wy*32, nb0 = wx*64;
    float c[2][8][4]; ZEROC(c);
    int lrow = (lane&7) + ((lane>>3)&1)*8;
    int lcolb = ((lane>>4)&1)*16;
    #pragma unroll
    for (int uu = 0; uu < 48; uu++) {
        int khalf = uu / 24, v = uu % 24;
        int idx = tid + 256*v;
        int comp = idx / 3072, rem = idx % 3072;
        int row = rem / 24, gr = rem % 24;
        int kg = khalf*24 + gr;
        const __nv_bfloat16* basep = comp ? g_Xlo : g_Xhi;
        size_t goff = (size_t)(tile*128 + row)*384 + kg*8;
        uint32_t dst = sb + comp*ALOP + row*PROW + kg*16;
        CPA16(dst, basep + goff);
        if (uu == 23) CPCOMMIT();
    }
    CPCOMMIT();
    const uint4* Fw = Pf + (size_t)p*12288 + wx*6144;
    #pragma unroll
    for (int half = 0; half < 2; half++) {
        if (half == 0) CPWAIT1(); else CPWAIT();
        __syncthreads();
        #pragma unroll
        for (int ks = half*12; ks < half*12+12; ks++) {
            uint32_t ah[2][4], al[2][4];
            #pragma unroll
            for (int mt = 0; mt < 2; mt++) {
                uint32_t adr = sb + (rb + mt*16 + lrow)*PROW + ks*32 + lcolb;
                ldmx4(adr, ah[mt][0], ah[mt][1], ah[mt][2], ah[mt][3]);
                adr += ALOP;
                ldmx4(adr, al[mt][0], al[mt][1], al[mt][2], al[mt][3]);
            }
            uint4 f4 = Fw[(ks*8)*32 + lane];
            #pragma unroll
            for (int nt = 0; nt < 8; nt++) {
                uint4 cur = f4;
                if (nt < 7) f4 = Fw[(ks*8 + nt + 1)*32 + lane];
                #pragma unroll
                for (int mt = 0; mt < 2; mt++) {
                    mma16816(c[mt][nt], ah[mt], cur.x, cur.y);
                    mma16816(c[mt][nt], ah[mt], cur.z, cur.w);
                    mma16816(c[mt][nt], al[mt], cur.x, cur.y);
                }
            }
        }
    }
    float* Out = (p==0) ? g_Vrow : (p==1) ? g_Vcol : g_Dd;
    int g = lane>>2, t2 = (lane&3)*2;
    #pragma unroll
    for (int mt = 0; mt < 2; mt++)
        #pragma unroll
        for (int h = 0; h < 2; h++) {
            int row = rb + mt*16 + g + h*8;
            int m = tile*128 + row;
            #pragma unroll
            for (int nt = 0; nt < 8; nt++) {
                int col = nb0 + nt*8 + t2;
                float2 v;
                v.x = c[mt][nt][h*2+0];
                v.y = c[mt][nt][h*2+1];
                *(float2*)(Out + (size_t)m*128 + col) = v;
            }
        }
}

// ---------------- initial T ----------------
__global__ void k_init(const float* __restrict__ momenta, const int* __restrict__ nobj,
                       const float* __restrict__ w_lin, const float* __restrict__ alpha,
                       const float* __restrict__ b_in) {
    int b = blockIdx.x / N_, i = blockIdx.x % N_;
    int nb = nobj[b];
    if (i >= nb) return;
    int tid = threadIdx.x;
    int c = tid & 127, jh = tid >> 7;
    __shared__ float pm[N_][4];
    __shared__ float dij[N_];
    __shared__ float y1s[N_][CS_];
    __shared__ float y0r[CS_], y2r[CS_], y3s[CS_], y4s[CS_];
    if (tid < 256) pm[tid>>2][tid&3] = momenta[(b*N_)*4 + tid];
    for (int idx = tid; idx < N_*CS_; idx += 256) {
        int n = idx/CS_, cs = idx%CS_;
        y1s[n][cs] = g_y012[((b*N_+n)*3+1)*CS_+cs];
    }
    if (tid < CS_) {
        y0r[tid] = g_y012[((b*N_+i)*3+0)*CS_+tid];
        y2r[tid] = g_y012[((b*N_+i)*3+2)*CS_+tid];
    } else if (tid < 2*CS_) {
        y3s[tid-CS_] = g_y34[(b*2+0)*CS_+tid-CS_];
    } else if (tid < 3*CS_) {
        y4s[tid-2*CS_] = g_y34[(b*2+1)*CS_+tid-2*CS_];
    }
    __syncthreads();
    if (tid < N_)
        dij[tid] = pm[i][0]*pm[tid][0] - pm[i][1]*pm[tid][1]
                 - pm[i][2]*pm[tid][2] - pm[i][3]*pm[tid][3];
    __syncthreads();
    float base = 0.f, wl = 0.f, al = 0.f;
    if (c < CS_) base = y0r[c] + y3s[c] + b_in[c];
    else { wl = w_lin[c-CS_]; al = alpha[c-CS_]; }
    size_t rowbase = ((size_t)(b*32 + (i>>1))*128 + (i&1)*64)*128;
    for (int j = jh; j < N_; j += 2) {
        float mask = (j < nb) ? 1.f : 0.f;
        float v;
        if (c < CS_) {
            v = base + y1s[j][c];
            if (j == i) v += y2r[c] + y4s[c];
            v = lrelu(v) * mask;
        } else {
            float r = dij[j] * wl;
            v = al * copysignf(log1pf(fabsf(r)), r) * mask;
        }
        __nv_bfloat16 h, l;
        split2(v, h, l);
        g_Ahi[rowbase + j*128 + c] = h;
        g_Alo[rowbase + j*128 + c] = l;
    }
}

// ---------------- col-sum reduction only: U -> X cvec ----------------
__global__ void k_r1c(const __nv_bfloat16* __restrict__ Uhi,
                      const __nv_bfloat16* __restrict__ Ulo,
                      const int* __restrict__ nobj) {
    int b = blockIdx.x >> 6, i = blockIdx.x & 63;
    if (i >= nobj[b]) return;
    int t = threadIdx.x;
    int g = t & 15, jg = t >> 4;
    __shared__ float redC[16][128];
    float aC[8] = {0,0,0,0,0,0,0,0};
    #pragma unroll
    for (int jj = 0; jj < 4; jj++) {
        int j = jg*4 + jj;
        size_t off = ((size_t)(b*32 + (j>>1))*128 + (j&1)*64 + i)*128 + g*8;
        uint4 h4 = *(const uint4*)(Uhi + off);
        uint4 l4 = *(const uint4*)(Ulo + off);
        const __nv_bfloat16 *hp = (const __nv_bfloat16*)&h4, *lp = (const __nv_bfloat16*)&l4;
        #pragma unroll
        for (int q = 0; q < 8; q++) aC[q] += __bfloat162float(hp[q]) + __bfloat162float(lp[q]);
    }
    #pragma unroll
    for (int q = 0; q < 8; q++) redC[jg][g*8+q] = aC[q];
    __syncthreads();
    if (t < 128) {
        float s = 0.f;
        #pragma unroll
        for (int r = 0; r < 16; r++) s += redC[r][t];
        size_t m = (size_t)(b*N_+i);
        __nv_bfloat16 h, l; split2(s / AVGF, h, l);
        g_Xhi[m*384 + 256 + t] = h; g_Xlo[m*384 + 256 + t] = l;
    }
}

// ---------------- output head (resets accumulators) ----------------
__global__ void k_out(const float* __restrict__ w20, const float* __restrict__ b20,
                      const float* __restrict__ wmlp, const float* __restrict__ bmlp,
                      float* __restrict__ out) {
    int b = blockIdx.x, d = threadIdx.x;
    __shared__ float a0[C_], a1[C_], act[C_];
    a0[d] = lrelu(g_dg[b*C_+d] / AVGF);
    a1[d] = lrelu(g_tot[b*C_+d] / (AVGF*AVGF));
    g_dg[b*C_+d] = 0.f;
    g_tot[b*C_+d] = 0.f;
    __syncthreads();
    float a = b20[d];
    for (int c = 0; c < C_; c++) a += a0[c]*w20[c*C_+d] + a1[c]*w20[(C_+c)*C_+d];
    act[d] = a;
    __syncthreads();
    if (d < 2) {
        float o = bmlp[d];
        for (int k = 0; k < C_; k++) o += act[k]*wmlp[k*2+d];
        out[b*2+d] = o;
    }
}

// ---------------- host ----------------
extern "C" void kernel_launch(void* const* d_in, const int* in_sizes, int n_in,
                              void* d_out, int out_size) {
    const float *momenta=0, *scalars=0, *w_lin=0, *alpha=0, *w_in=0, *b_in=0;
    const int* nobj=0;
    const float *msgw[4], *msgb[4], *eqw[4], *eqb[4], *eqbd[4];
    const float *wm0=0, *bm0=0, *w20=0, *b20=0, *wmlp=0, *bmlp=0;

    if (n_in >= 33 && in_sizes[0] == 8192) {
        momenta=(const float*)d_in[0]; scalars=(const float*)d_in[1]; nobj=(const int*)d_in[2];
        w_lin=(const float*)d_in[3]; alpha=(const float*)d_in[4]; w_in=(const float*)d_in[5];
        b_in=(const float*)d_in[6];
        for (int l = 0; l < 4; l++) {
            msgw[l]=(const float*)d_in[7+l];  msgb[l]=(const float*)d_in[11+l];
            eqw[l] =(const float*)d_in[15+l]; eqb[l] =(const float*)d_in[19+l];
            eqbd[l]=(const float*)d_in[23+l];
        }
        wm0=(const float*)d_in[27]; bm0=(const float*)d_in[28]; w20=(const float*)d_in[29];
        b20=(const float*)d_in[30]; wmlp=(const float*)d_in[31]; bmlp=(const float*)d_in[32];
    } else if (n_in >= 33) {
        alpha=(const float*)d_in[0]; b20=(const float*)d_in[1]; b_in=(const float*)d_in[2];
        bm0=(const float*)d_in[3]; bmlp=(const float*)d_in[4];
        for (int l = 0; l < 4; l++) {
            eqb[l] =(const float*)d_in[5+l];  eqbd[l]=(const float*)d_in[9+l];
            eqw[l] =(const float*)d_in[13+l]; msgb[l]=(const float*)d_in[18+l];
            msgw[l]=(const float*)d_in[22+l];
        }
        momenta=(const float*)d_in[17]; nobj=(const int*)d_in[26]; scalars=(const float*)d_in[27];
        w20=(const float*)d_in[28]; w_in=(const float*)d_in[29]; w_lin=(const float*)d_in[30];
        wm0=(const float*)d_in[31]; wmlp=(const float*)d_in[32];
    } else {
        momenta=(const float*)d_in[0]; scalars=(const float*)d_in[1]; nobj=(const int*)d_in[2];
        w_lin=(const float*)d_in[3]; alpha=(const float*)d_in[4]; w_in=(const float*)d_in[5];
        b_in=(const float*)d_in[6];
        for (int l = 0; l < 4; l++) {
            msgw[l]=(const float*)d_in[7]+(size_t)l*C_*C_;     msgb[l]=(const float*)d_in[8]+(size_t)l*C_;
            eqw[l] =(const float*)d_in[9]+(size_t)l*15*C_*C_;  eqb[l] =(const float*)d_in[10]+(size_t)l*C_;
            eqbd[l]=(const float*)d_in[11]+(size_t)l*C_;
        }
        wm0=(const float*)d_in[12]; bm0=(const float*)d_in[13]; w20=(const float*)d_in[14];
        b20=(const float*)d_in[15]; wmlp=(const float*)d_in[16]; bmlp=(const float*)d_in[17];
    }

    cudaFuncSetAttribute(k_gemm0, cudaFuncAttributeMaxDynamicSharedMemorySize, SM_G);
    cudaFuncSetAttribute(k_gemm2, cudaFuncAttributeMaxDynamicSharedMemorySize, SM_G);
    cudaFuncSetAttribute(k_proj,  cudaFuncAttributeMaxDynamicSharedMemorySize, SM_P);

    __nv_bfloat16 *Ahi=0, *Alo=0, *Bhi=0, *Blo=0;
    uint4 *Bf=0, *Pf=0;
    cudaGetSymbolAddress((void**)&Ahi, g_Ahi);
    cudaGetSymbolAddress((void**)&Alo, g_Alo);
    cudaGetSymbolAddress((void**)&Bhi, g_Bhi);
    cudaGetSymbolAddress((void**)&Blo, g_Blo);
    cudaGetSymbolAddress((void**)&Bf,  g_Bf);
    cudaGetSymbolAddress((void**)&Pf,  g_Pf);

    k_setup<<<132, 256>>>(msgw[0], msgw[1], msgw[2], msgw[3],
                          eqw[0], eqw[1], eqw[2], eqw[3], wm0,
                          scalars, nobj, w_in);
    k_init<<<B_*N_, 256>>>(momenta, nobj, w_lin, alpha, b_in);

    k_gemm0<<<TILES, 256, SM_G>>>(Ahi, Alo, Bf + 0*4096, msgb[0], nobj, Bhi, Blo);

    __nv_bfloat16 *curHi = Bhi, *curLo = Blo, *nxtHi = Ahi, *nxtLo = Alo;
    for (int l = 0; l < 4; l++) {
        k_r1c<<<B_*N_, 256>>>(curHi, curLo, nobj);
        k_proj<<<80, 256, SM_P>>>(Pf + (size_t)(l*3)*12288,
                                  eqw[l], eqb[l], eqbd[l], nobj);
        if (l < 3) {
            k_gemm2<<<TILES, 256, SM_G>>>(curHi, curLo,
                                          Bf + (4 + l*2)*4096, Bf + (5 + l*2)*4096,
                                          Bf + (l+1)*4096, msgb[l+1], nobj, 0,
                                          nxtHi, nxtLo);
            __nv_bfloat16* th = curHi; curHi = nxtHi; nxtHi = th;
            __nv_bfloat16* tl = curLo; curLo = nxtLo; nxtLo = tl;
        } else {
            k_gemm2<<<TILES, 256, SM_G>>>(curHi, curLo,
                                          Bf + (4 + l*2)*4096, Bf + (5 + l*2)*4096,
                                          Bf + 12*4096, bm0, nobj, 3,
                                          (__nv_bfloat16*)0, (__nv_bfloat16*)0);
        }
    }

    k_out<<<B_, 128>>>(w20, b20, wmlp, bmlp, (float*)d_out);
}

// round 16
// speedup vs baseline: 1.1539x; 1.0181x over previous
#include <cuda_runtime.h>
#include <cuda_bf16.h>
#include <math.h>
#include <stdint.h>

#define B_  32
#define N_  64
#define S_  9
#define C_  128
#define CS_ 32
#define AVGF 49.0f
#define TILES (B_*32)

// ---------------- device scratch ----------------
__device__ __nv_bfloat16 g_Ahi[TILES*16384], g_Alo[TILES*16384];
__device__ __nv_bfloat16 g_Bhi[TILES*16384], g_Blo[TILES*16384];
__device__ __nv_bfloat16 g_Xhi[B_*N_*384], g_Xlo[B_*N_*384];
__device__ uint4 g_Bf[13*4096];
__device__ uint4 g_Pf[12*12288];
__device__ float g_y012[B_*N_*3*CS_];
__device__ float g_y34[B_*2*CS_];
__device__ float g_Vrow[B_*N_*C_];
__device__ float g_Vcol[B_*N_*C_];
__device__ float g_Dd[B_*N_*C_];
__device__ float g_G[B_*C_];
__device__ float g_E[B_*C_];
__device__ float g_dg[B_*C_];
__device__ float g_tot[B_*C_];

__device__ __forceinline__ float lrelu(float x){ return x >= 0.f ? x : 0.01f*x; }
__device__ __forceinline__ uint32_t smem_u32(const void* p) {
    uint32_t a;
    asm("{ .reg .u64 t; cvta.to.shared.u64 t, %1; cvt.u32.u64 %0, t; }" : "=r"(a) : "l"(p));
    return a;
}
__device__ __forceinline__ void split2(float v, __nv_bfloat16& h, __nv_bfloat16& l) {
    h = __float2bfloat16(v);
    l = __float2bfloat16(v - __bfloat162float(h));
}
__device__ __forceinline__ uint32_t packbf(__nv_bfloat16 a, __nv_bfloat16 b) {
    __nv_bfloat162 p; p.x = a; p.y = b;
    return *(uint32_t*)&p;
}
__device__ __forceinline__ void ldmx4(uint32_t a, uint32_t& r0, uint32_t& r1, uint32_t& r2, uint32_t& r3) {
    asm volatile("ldmatrix.sync.aligned.m8n8.x4.shared.b16 {%0,%1,%2,%3}, [%4];"
                 : "=r"(r0), "=r"(r1), "=r"(r2), "=r"(r3) : "r"(a));
}
__device__ __forceinline__ void mma16816(float* c, const uint32_t* a, uint32_t b0, uint32_t b1) {
    asm volatile("mma.sync.aligned.m16n8k16.row.col.f32.bf16.bf16.f32 "
                 "{%0,%1,%2,%3}, {%4,%5,%6,%7}, {%8,%9}, {%0,%1,%2,%3};"
                 : "+f"(c[0]), "+f"(c[1]), "+f"(c[2]), "+f"(c[3])
                 : "r"(a[0]), "r"(a[1]), "r"(a[2]), "r"(a[3]), "r"(b0), "r"(b1));
}
#define CPA16(dst, src) asm volatile("cp.async.ca.shared.global [%0], [%1], 16;" :: "r"(dst), "l"(src))
#define CPCOMMIT() asm volatile("cp.async.commit_group;" ::: "memory")
#define CPWAIT1()  asm volatile("cp.async.wait_group 1;"  ::: "memory")
#define CPWAIT()   asm volatile("cp.async.wait_group 0;"  ::: "memory")

#define ALO2  34816
#define SM_G  69632
#define SM_G0 81920
#define PROW  784
#define ALOP  100352
#define SM_P  200704

// ---------------- one-time setup ----------------
__global__ void k_setup(const float* __restrict__ m0, const float* __restrict__ m1,
                        const float* __restrict__ m2, const float* __restrict__ m3,
                        const float* __restrict__ e0, const float* __restrict__ e1,
                        const float* __restrict__ e2, const float* __restrict__ e3,
                        const float* __restrict__ wfin,
                        const float* __restrict__ scalars, const int* __restrict__ nobj,
                        const float* __restrict__ w_in) {
    int blk = blockIdx.x, tid = threadIdx.x;
    if (blk < 52) {
        int mat = blk >> 2, quar = blk & 3;
        const float* W;
        if (mat < 4)       W = (mat==0)?m0:(mat==1)?m1:(mat==2)?m2:m3;
        else if (mat < 12) {
            int l = (mat-4)>>1, wh = (mat-4)&1;
            const float* E = (l==0)?e0:(l==1)?e1:(l==2)?e2:e3;
            W = E + wh*16384;
        } else W = wfin;
        uint4* dst = g_Bf + mat*4096;
        for (int e = quar*1024 + tid; e < quar*1024 + 1024; e += 256) {
            int lane = e&31, nt = (e>>5)&7, ks = (e>>8)&7, wx = e>>11;
            int n = wx*64 + nt*8 + (lane>>2);
            int k0 = ks*16 + (lane&3)*2;
            __nv_bfloat16 h00,l00,h01,l01,h10,l10,h11,l11;
            split2(W[k0*128+n],     h00, l00);
            split2(W[(k0+1)*128+n], h01, l01);
            split2(W[(k0+8)*128+n], h10, l10);
            split2(W[(k0+9)*128+n], h11, l11);
            uint4 o;
            o.x = packbf(h00,h01); o.y = packbf(h10,h11);
            o.z = packbf(l00,l01); o.w = packbf(l10,l11);
            dst[e] = o;
        }
    } else if (blk < 100) {
        int idx = blk - 52;
        int unit = idx >> 2, quar = idx & 3;
        int l = unit / 3, p = unit % 3;
        const int tbl[3][3] = {{3,5,7},{4,6,8},{2,9,10}};
        const float* E = (l==0)?e0:(l==1)?e1:(l==2)?e2:e3;
        uint4* dst = g_Pf + (size_t)unit*12288;
        for (int e = quar*3072 + tid; e < quar*3072 + 3072; e += 256) {
            int wx = e / 6144, rem = e % 6144;
            int ks = rem >> 8, nt = (rem>>5)&7, lane = rem&31;
            int n = wx*64 + nt*8 + (lane>>2);
            int k0 = ks*16 + (lane&3)*2;
            __nv_bfloat16 hh[4], ll[4];
            #pragma unroll
            for (int q = 0; q < 4; q++) {
                int k = k0 + (q>>1)*8 + (q&1);
                int mat = tbl[p][k>>7], kk = k&127;
                split2(E[(mat*C_ + kk)*C_ + n], hh[q], ll[q]);
            }
            uint4 o;
            o.x = packbf(hh[0],hh[1]); o.y = packbf(hh[2],hh[3]);
            o.z = packbf(ll[0],ll[1]); o.w = packbf(ll[2],ll[3]);
            dst[e] = o;
        }
    } else {
        int b = blk - 100;
        __shared__ float xs[N_][S_];
        __shared__ float ssum[S_];
        int nb = nobj[b];
        for (int idx = tid; idx < N_*S_; idx += 256) {
            int n = idx/S_, s = idx%S_;
            xs[n][s] = (n < nb) ? scalars[(b*N_+n)*S_+s] : 0.f;
        }
        __syncthreads();
        if (tid < S_) {
            float a = 0.f;
            for (int n = 0; n < N_; n++) a += xs[n][tid];
            ssum[tid] = a / AVGF;
        }
        __syncthreads();
        for (int idx = tid; idx < N_*CS_; idx += 256) {
            int n = idx/CS_, c = idx%CS_;
            float a0=0, a1=0, a2=0;
            #pragma unroll
            for (int s = 0; s < S_; s++) {
                float xv = xs[n][s];
                a0 += xv*w_in[(0*S_+s)*CS_+c];
                a1 += xv*w_in[(1*S_+s)*CS_+c];
                a2 += xv*w_in[(2*S_+s)*CS_+c];
            }
            g_y012[((b*N_+n)*3+0)*CS_+c] = a0;
            g_y012[((b*N_+n)*3+1)*CS_+c] = a1;
            g_y012[((b*N_+n)*3+2)*CS_+c] = a2;
        }
        if (tid < 2*CS_) {
            int k = tid/CS_, c = tid%CS_;
            float a = 0.f;
            #pragma unroll
            for (int s = 0; s < S_; s++) a += ssum[s]*w_in[((3+k)*S_+s)*CS_+c];
            g_y34[(b*2+k)*CS_+c] = a;
        }
    }
}

// ---------------- GEMM helpers ----------------
struct GemmCtx {
    uint32_t sb;
    int tid, wid, lane, tile, b, i0, nb;
    int wy, wx, rb, nb0, lrow, lcolb, g, t2;
};
__device__ __forceinline__ void stage_src(const GemmCtx& X, const __nv_bfloat16* Ahi,
                                          const __nv_bfloat16* Alo, bool transp) {
    #pragma unroll
    for (int uu = 0; uu < 16; uu++) {
        int group = uu>>3, comp = (uu>>2)&1, sub = uu&3;
        int f = X.tid + 256*(comp*8 + group*4 + sub);
        int idx = f & 2047;
        int row = (idx>>3)&127, c8 = idx&7, c16 = group*8 + c8;
        const __nv_bfloat16* basep = comp ? Alo : Ahi;
        size_t goff;
        if (!transp) {
            goff = (size_t)X.tile*16384 + row*128 + c16*8;
        } else {
            int jj = row&63, hh = row>>6;
            goff = ((size_t)(X.b*32 + (jj>>1))*128 + (jj&1)*64 + X.i0 + hh)*128 + c16*8;
        }
        uint32_t dst = X.sb + comp*ALO2 + row*272 + c16*16;
        CPA16(dst, basep + goff);
        if (uu == 7) CPCOMMIT();
    }
    CPCOMMIT();
}
__device__ __forceinline__ void compute_pass(const GemmCtx& X, const uint4* Fw,
                                             float c[2][8][4], bool staged) {
    #pragma unroll
    for (int half = 0; half < 2; half++) {
        if (staged) { if (half == 0) CPWAIT1(); else CPWAIT(); __syncthreads(); }
        #pragma unroll
        for (int ks = half*4; ks < half*4+4; ks++) {
            uint32_t ah[2][4], al[2][4];
            #pragma unroll
            for (int mt = 0; mt < 2; mt++) {
                uint32_t adr = X.sb + (X.rb + mt*16 + X.lrow)*272 + ks*32 + X.lcolb;
                ldmx4(adr, ah[mt][0], ah[mt][1], ah[mt][2], ah[mt][3]);
                adr += ALO2;
                ldmx4(adr, al[mt][0], al[mt][1], al[mt][2], al[mt][3]);
            }
            uint4 f4 = Fw[(ks*8)*32 + X.lane];
            #pragma unroll
            for (int nt = 0; nt < 8; nt++) {
                uint4 cur = f4;
                if (nt < 7) f4 = Fw[(ks*8 + nt + 1)*32 + X.lane];
                #pragma unroll
                for (int mt = 0; mt < 2; mt++) {
                    mma16816(c[mt][nt], ah[mt], cur.x, cur.y);
                    mma16816(c[mt][nt], ah[mt], cur.z, cur.w);
                    mma16816(c[mt][nt], al[mt], cur.x, cur.y);
                }
            }
        }
    }
}
__device__ __forceinline__ void init_ctx(GemmCtx& X, unsigned char* sm) {
    X.sb = smem_u32(sm);
    X.tid = threadIdx.x; X.wid = X.tid>>5; X.lane = X.tid&31;
    X.tile = blockIdx.x; X.b = X.tile>>5; X.i0 = (X.tile&31)<<1;
    X.wy = X.wid&3; X.wx = X.wid>>2;
    X.rb = X.wy*32; X.nb0 = X.wx*64;
    X.lrow = (X.lane&7) + ((X.lane>>3)&1)*8;
    X.lcolb = ((X.lane>>4)&1)*16;
    X.g = X.lane>>2; X.t2 = (X.lane&3)*2;
}
#define ZEROC(c) { _Pragma("unroll") for (int mt=0;mt<2;mt++) _Pragma("unroll") for (int nt=0;nt<8;nt++) _Pragma("unroll") for (int q=0;q<4;q++) c[mt][nt][q]=0.f; }

// epilogue: write U (bf16 hi/lo) + rvec/dvec into X (atomic-free; tile-local)
__device__ __forceinline__ void epilogue_UX(const GemmCtx& X, float c[2][8][4],
                                            const float* bias,
                                            __nv_bfloat16* OutHi, __nv_bfloat16* OutLo,
                                            unsigned char* sm) {
    __syncthreads();
    float* Vs = (float*)sm;   // [128][132]
    __nv_bfloat16* Hi = OutHi + (size_t)X.tile*16384;
    __nv_bfloat16* Lo = OutLo + (size_t)X.tile*16384;
    #pragma unroll
    for (int mt = 0; mt < 2; mt++)
        #pragma unroll
        for (int h = 0; h < 2; h++) {
            int row = X.rb + mt*16 + X.g + h*8;
            int i = X.i0 + (row>>6), j = row&63;
            float mask = (i < X.nb && j < X.nb) ? 1.f : 0.f;
            #pragma unroll
            for (int nt = 0; nt < 8; nt++) {
                int col = X.nb0 + nt*8 + X.t2;
                float vx = lrelu(c[mt][nt][h*2+0] + bias[col])   * mask;
                float vy = lrelu(c[mt][nt][h*2+1] + bias[col+1]) * mask;
                __nv_bfloat16 hx,lx,hy,ly;
                split2(vx, hx, lx); split2(vy, hy, ly);
                *(uint32_t*)(Hi + row*128 + col) = packbf(hx, hy);
                *(uint32_t*)(Lo + row*128 + col) = packbf(lx, ly);
                float2 v; v.x = vx; v.y = vy;
                *(float2*)(Vs + row*132 + col) = v;
            }
        }
    __syncthreads();
    int t = X.tid;
    int half = t >> 7, cc = t & 127;
    float s = 0.f;
    #pragma unroll 8
    for (int r = 0; r < 64; r++) s += Vs[(half*64 + r)*132 + cc];
    size_t m = (size_t)(X.b*64 + X.i0 + half);
    __nv_bfloat16 h, l;
    split2(s / AVGF, h, l);
    g_Xhi[m*384 + 128 + cc] = h; g_Xlo[m*384 + 128 + cc] = l;
    split2(Vs[(half*64 + X.i0 + half)*132 + cc], h, l);
    g_Xhi[m*384 + cc] = h; g_Xlo[m*384 + cc] = l;
}

// ---------------- mode-0 GEMM with fused T-init (no global T) ----------------
__global__ void __launch_bounds__(256, 2) k_gemm0(const float* __restrict__ momenta,
                                                  const float* __restrict__ w_lin,
                                                  const float* __restrict__ alpha,
                                                  const float* __restrict__ b_in,
                                                  const uint4* __restrict__ F,
                                                  const float* __restrict__ bias,
                                                  const int* __restrict__ nobj,
                                                  __nv_bfloat16* __restrict__ OutHi,
                                                  __nv_bfloat16* __restrict__ OutLo) {
    extern __shared__ unsigned char sm[];
    GemmCtx X; init_ctx(X, sm);
    X.nb = nobj[X.b];
    if (X.i0 >= X.nb) return;
    int tid = X.tid, b = X.b, i0 = X.i0, nb = X.nb;
    // aux region after A buffers
    float* aux = (float*)(sm + SM_G);
    float* pm  = aux;            // [64][4]
    float* dij = aux + 256;      // [2][64]
    float* y1s = aux + 384;      // [64][32]
    float* y0r = aux + 2432;     // [2][32]
    float* y2r = aux + 2496;     // [2][32]
    float* y3s = aux + 2560;     // [32]
    float* y4s = aux + 2592;     // [32]
    pm[tid] = momenta[b*256 + tid];
    for (int idx = tid; idx < 2048; idx += 256)
        y1s[idx] = g_y012[((b*64 + (idx>>5))*3 + 1)*32 + (idx&31)];
    if (tid < 64) {
        int h = tid>>5, c = tid&31;
        y0r[tid] = g_y012[((b*64+i0+h)*3+0)*32+c];
        y2r[tid] = g_y012[((b*64+i0+h)*3+2)*32+c];
    } else if (tid < 96) {
        y3s[tid-64] = g_y34[(b*2+0)*32 + tid-64];
    } else if (tid < 128) {
        y4s[tid-96] = g_y34[(b*2+1)*32 + tid-96];
    }
    __syncthreads();
    if (tid < 128) {
        int h = tid>>6, j = tid&63;
        const float* pi = pm + (i0+h)*4;
        const float* pj = pm + j*4;
        dij[tid] = pi[0]*pj[0] - pi[1]*pj[1] - pi[2]*pj[2] - pi[3]*pj[3];
    }
    __syncthreads();
    {
        int c2 = tid & 63, rh = tid >> 6;
        int c0 = c2*2;
        int h = rh >> 1, i = i0 + h;
        bool iact = (i < nb);
        float bx=0, by=0, d2x=0, d2y=0, wlx=0, wly=0, alx=0, aly=0;
        if (c2 < 16) {
            bx = y0r[h*32+c0]   + y3s[c0]   + b_in[c0];
            by = y0r[h*32+c0+1] + y3s[c0+1] + b_in[c0+1];
            d2x = y2r[h*32+c0]   + y4s[c0];
            d2y = y2r[h*32+c0+1] + y4s[c0+1];
        } else {
            wlx = w_lin[c0-32]; wly = w_lin[c0-31];
            alx = alpha[c0-32]; aly = alpha[c0-31];
        }
        #pragma unroll 4
        for (int it = 0; it < 32; it++) {
            int j = (rh&1)*32 + it;
            int row = h*64 + j;
            float mask = (iact && j < nb) ? 1.f : 0.f;
            float vx, vy;
            if (c2 < 16) {
                vx = bx + y1s[j*32+c0];
                vy = by + y1s[j*32+c0+1];
                if (j == i) { vx += d2x; vy += d2y; }
                vx = lrelu(vx) * mask;
                vy = lrelu(vy) * mask;
            } else {
                float d = dij[h*64+j];
                float rx = d*wlx, ry = d*wly;
                vx = alx * copysignf(log1pf(fabsf(rx)), rx) * mask;
                vy = aly * copysignf(log1pf(fabsf(ry)), ry) * mask;
            }
            __nv_bfloat16 hx,lx,hy,ly;
            split2(vx, hx, lx); split2(vy, hy, ly);
            *(uint32_t*)(sm + row*272 + c0*2)        = packbf(hx, hy);
            *(uint32_t*)(sm + ALO2 + row*272 + c0*2) = packbf(lx, ly);
        }
    }
    __syncthreads();
    float c[2][8][4]; ZEROC(c);
    compute_pass(X, F + X.wx*2048, c, false);
    epilogue_UX(X, c, bias, OutHi, OutLo, sm);
}

// ---------------- fused GEMM: Eq2to2 dual + combine -> T(smem) -> next GEMM ----------
__global__ void __launch_bounds__(256, 2) k_gemm2(const __nv_bfloat16* __restrict__ Uhi,
                                                  const __nv_bfloat16* __restrict__ Ulo,
                                                  const uint4* __restrict__ F0,
                                                  const uint4* __restrict__ F1,
                                                  const uint4* __restrict__ F2,
                                                  const float* __restrict__ bias2,
                                                  const int* __restrict__ nobj, int mode2,
                                                  __nv_bfloat16* __restrict__ OutHi,
                                                  __nv_bfloat16* __restrict__ OutLo) {
    extern __shared__ unsigned char sm[];
    GemmCtx X; init_ctx(X, sm);
    X.nb = nobj[X.b];
    if (X.i0 >= X.nb) return;
    float c[2][8][4]; ZEROC(c);
    stage_src(X, Uhi, Ulo, false);
    compute_pass(X, F0 + X.wx*2048, c, true);
    __syncthreads();
    stage_src(X, Uhi, Ulo, true);
    compute_pass(X, F1 + X.wx*2048, c, true);
    __syncthreads();
    #pragma unroll
    for (int mt = 0; mt < 2; mt++)
        #pragma unroll
        for (int h = 0; h < 2; h++) {
            int row = X.rb + mt*16 + X.g + h*8;
            int i = X.i0 + (row>>6), j = row&63;
            float mask = (i < X.nb && j < X.nb) ? 1.f : 0.f;
            bool diag = (i == j);
            const float* vr = g_Vrow + (X.b*64+i)*C_;
            const float* vc = g_Vcol + (X.b*64+j)*C_;
            const float* gg = g_G + X.b*C_;
            const float* dd = g_Dd + (X.b*64+i)*C_;
            const float* ee = g_E + X.b*C_;
            #pragma unroll
            for (int nt = 0; nt < 8; nt++) {
                int col = X.nb0 + nt*8 + X.t2;
                float vx = c[mt][nt][h*2+0] + vr[col]   + gg[col]   + vc[col];
                float vy = c[mt][nt][h*2+1] + vr[col+1] + gg[col+1] + vc[col+1];
                if (diag) { vx += dd[col] + ee[col]; vy += dd[col+1] + ee[col+1]; }
                vx = lrelu(vx) * mask;
                vy = lrelu(vy) * mask;
                __nv_bfloat16 hx,lx,hy,ly;
                split2(vx, hx, lx); split2(vy, hy, ly);
                *(uint32_t*)(sm + row*272 + col*2)        = packbf(hx, hy);
                *(uint32_t*)(sm + ALO2 + row*272 + col*2) = packbf(lx, ly);
            }
        }
    __syncthreads();
    ZEROC(c);
    compute_pass(X, F2 + X.wx*2048, c, false);
    if (mode2 == 0) {
        epilogue_UX(X, c, bias2, OutHi, OutLo, sm);
    } else {
        __syncthreads();
        float* Vs = (float*)sm;
        #pragma unroll
        for (int mt = 0; mt < 2; mt++)
            #pragma unroll
            for (int h = 0; h < 2; h++) {
                int row = X.rb + mt*16 + X.g + h*8;
                int i = X.i0 + (row>>6), j = row&63;
                float mask = (i < X.nb && j < X.nb) ? 1.f : 0.f;
                #pragma unroll
                for (int nt = 0; nt < 8; nt++) {
                    int col = X.nb0 + nt*8 + X.t2;
                    float2 v;
                    v.x = lrelu(c[mt][nt][h*2+0] + bias2[col])   * mask;
                    v.y = lrelu(c[mt][nt][h*2+1] + bias2[col+1]) * mask;
                    *(float2*)(Vs + row*132 + col) = v;
                }
            }
        __syncthreads();
        if (X.tid < 128) {
            float s = 0.f;
            #pragma unroll 8
            for (int r = 0; r < 128; r++) s += Vs[r*132 + X.tid];
            atomicAdd(&g_tot[X.b*C_ + X.tid], s);
            float dgv = Vs[X.i0*132 + X.tid] + Vs[(64 + X.i0 + 1)*132 + X.tid];
            atomicAdd(&g_dg[X.b*C_ + X.tid], dgv);
        }
    }
}

// ---------------- proj GEMM (fragment B, full-K cp.async A) + fused G/E --------------
__global__ void __launch_bounds__(256, 1) k_proj(const uint4* __restrict__ Pf,
                                                 const float* __restrict__ W,
                                                 const float* __restrict__ eqb,
                                                 const float* __restrict__ eqbd,
                                                 const int* __restrict__ nobj) {
    extern __shared__ unsigned char sm[];
    if (blockIdx.x >= 48) {
        int b = blockIdx.x - 48, d = threadIdx.x;
        float* tt = (float*)sm;
        float* tg = (float*)sm + 128;
        if (d < 128) {
            int nb = nobj[b];
            float t = 0.f, tr = 0.f;
            for (int i = 0; i < nb; i++) {
                size_t m = (size_t)(b*N_+i);
                t  += __bfloat162float(g_Xhi[m*384 + 128 + d]) + __bfloat162float(g_Xlo[m*384 + 128 + d]);
                tr += __bfloat162float(g_Xhi[m*384 + d])       + __bfloat162float(g_Xlo[m*384 + d]);
            }
            tt[d] = t / AVGF; tg[d] = tr / AVGF;
        }
        __syncthreads();
        if (d < 128) {
            float g = eqb[d], e = eqbd[d];
            for (int c = 0; c < C_; c++) {
                g += tt[c]*W[(11*C_+c)*C_+d] + tg[c]*W[(13*C_+c)*C_+d];
                e += tt[c]*W[(12*C_+c)*C_+d] + tg[c]*W[(14*C_+c)*C_+d];
            }
            g_G[b*C_+d] = g; g_E[b*C_+d] = e;
        }
        return;
    }
    uint32_t sb = smem_u32(sm);
    int tid = threadIdx.x, wid = tid>>5, lane = tid&31;
    int p = blockIdx.x >> 4, tile = blockIdx.x & 15;
    int wy = wid&3, wx = wid>>2;
    int rb = wy*32, nb0 = wx*64;
    float c[2][8][4]; ZEROC(c);
    int lrow = (lane&7) + ((lane>>3)&1)*8;
    int lcolb = ((lane>>4)&1)*16;
    #pragma unroll
    for (int uu = 0; uu < 48; uu++) {
        int khalf = uu / 24, v = uu % 24;
        int idx = tid + 256*v;
        int comp = idx / 3072, rem = idx % 3072;
        int row = rem / 24, gr = rem % 24;
        int kg = khalf*24 + gr;
        const __nv_bfloat16* basep = comp ? g_Xlo : g_Xhi;
        size_t goff = (size_t)(tile*128 + row)*384 + kg*8;
        uint32_t dst = sb + comp*ALOP + row*PROW + kg*16;
        CPA16(dst, basep + goff);
        if (uu == 23) CPCOMMIT();
    }
    CPCOMMIT();
    const uint4* Fw = Pf + (size_t)p*12288 + wx*6144;
    #pragma unroll
    for (int half = 0; half < 2; half++) {
        if (half == 0) CPWAIT1(); else CPWAIT();
        __syncthreads();
        #pragma unroll
        for (int ks = half*12; ks < half*12+12; ks++) {
            uint32_t ah[2][4], al[2][4];
            #pragma unroll
            for (int mt = 0; mt < 2; mt++) {
                uint32_t adr = sb + (rb + mt*16 + lrow)*PROW + ks*32 + lcolb;
                ldmx4(adr, ah[mt][0], ah[mt][1], ah[mt][2], ah[mt][3]);
                adr += ALOP;
                ldmx4(adr, al[mt][0], al[mt][1], al[mt][2], al[mt][3]);
            }
            uint4 f4 = Fw[(ks*8)*32 + lane];
            #pragma unroll
            for (int nt = 0; nt < 8; nt++) {
                uint4 cur = f4;
                if (nt < 7) f4 = Fw[(ks*8 + nt + 1)*32 + lane];
                #pragma unroll
                for (int mt = 0; mt < 2; mt++) {
                    mma16816(c[mt][nt], ah[mt], cur.x, cur.y);
                    mma16816(c[mt][nt], ah[mt], cur.z, cur.w);
                    mma16816(c[mt][nt], al[mt], cur.x, cur.y);
                }
            }
        }
    }
    float* Out = (p==0) ? g_Vrow : (p==1) ? g_Vcol : g_Dd;
    int g = lane>>2, t2 = (lane&3)*2;
    #pragma unroll
    for (int mt = 0; mt < 2; mt++)
        #pragma unroll
        for (int h = 0; h < 2; h++) {
            int row = rb + mt*16 + g + h*8;
            int m = tile*128 + row;
            #pragma unroll
            for (int nt = 0; nt < 8; nt++) {
                int col = nb0 + nt*8 + t2;
                float2 v;
                v.x = c[mt][nt][h*2+0];
                v.y = c[mt][nt][h*2+1];
                *(float2*)(Out + (size_t)m*128 + col) = v;
            }
        }
}

// ---------------- col-sum reduction only: U -> X cvec (nb-bounded) ----------------
__global__ void k_r1c(const __nv_bfloat16* __restrict__ Uhi,
                      const __nv_bfloat16* __restrict__ Ulo,
                      const int* __restrict__ nobj) {
    int b = blockIdx.x >> 6, i = blockIdx.x & 63;
    int nb = nobj[b];
    if (i >= nb) return;
    int t = threadIdx.x;
    int g = t & 15, jg = t >> 4;
    __shared__ float redC[16][128];
    float aC[8] = {0,0,0,0,0,0,0,0};
    #pragma unroll
    for (int jj = 0; jj < 4; jj++) {
        int j = jg*4 + jj;
        if (j < nb) {
            size_t off = ((size_t)(b*32 + (j>>1))*128 + (j&1)*64 + i)*128 + g*8;
            uint4 h4 = *(const uint4*)(Uhi + off);
            uint4 l4 = *(const uint4*)(Ulo + off);
            const __nv_bfloat16 *hp = (const __nv_bfloat16*)&h4, *lp = (const __nv_bfloat16*)&l4;
            #pragma unroll
            for (int q = 0; q < 8; q++) aC[q] += __bfloat162float(hp[q]) + __bfloat162float(lp[q]);
        }
    }
    #pragma unroll
    for (int q = 0; q < 8; q++) redC[jg][g*8+q] = aC[q];
    __syncthreads();
    if (t < 128) {
        float s = 0.f;
        #pragma unroll
        for (int r = 0; r < 16; r++) s += redC[r][t];
        size_t m = (size_t)(b*N_+i);
        __nv_bfloat16 h, l; split2(s / AVGF, h, l);
        g_Xhi[m*384 + 256 + t] = h; g_Xlo[m*384 + 256 + t] = l;
    }
}

// ---------------- output head (resets accumulators) ----------------
__global__ void k_out(const float* __restrict__ w20, const float* __restrict__ b20,
                      const float* __restrict__ wmlp, const float* __restrict__ bmlp,
                      float* __restrict__ out) {
    int b = blockIdx.x, d = threadIdx.x;
    __shared__ float a0[C_], a1[C_], act[C_];
    a0[d] = lrelu(g_dg[b*C_+d] / AVGF);
    a1[d] = lrelu(g_tot[b*C_+d] / (AVGF*AVGF));
    g_dg[b*C_+d] = 0.f;
    g_tot[b*C_+d] = 0.f;
    __syncthreads();
    float a = b20[d];
    for (int c = 0; c < C_; c++) a += a0[c]*w20[c*C_+d] + a1[c]*w20[(C_+c)*C_+d];
    act[d] = a;
    __syncthreads();
    if (d < 2) {
        float o = bmlp[d];
        for (int k = 0; k < C_; k++) o += act[k]*wmlp[k*2+d];
        out[b*2+d] = o;
    }
}

// ---------------- host ----------------
extern "C" void kernel_launch(void* const* d_in, const int* in_sizes, int n_in,
                              void* d_out, int out_size) {
    const float *momenta=0, *scalars=0, *w_lin=0, *alpha=0, *w_in=0, *b_in=0;
    const int* nobj=0;
    const float *msgw[4], *msgb[4], *eqw[4], *eqb[4], *eqbd[4];
    const float *wm0=0, *bm0=0, *w20=0, *b20=0, *wmlp=0, *bmlp=0;

    if (n_in >= 33 && in_sizes[0] == 8192) {
        momenta=(const float*)d_in[0]; scalars=(const float*)d_in[1]; nobj=(const int*)d_in[2];
        w_lin=(const float*)d_in[3]; alpha=(const float*)d_in[4]; w_in=(const float*)d_in[5];
        b_in=(const float*)d_in[6];
        for (int l = 0; l < 4; l++) {
            msgw[l]=(const float*)d_in[7+l];  msgb[l]=(const float*)d_in[11+l];
            eqw[l] =(const float*)d_in[15+l]; eqb[l] =(const float*)d_in[19+l];
            eqbd[l]=(const float*)d_in[23+l];
        }
        wm0=(const float*)d_in[27]; bm0=(const float*)d_in[28]; w20=(const float*)d_in[29];
        b20=(const float*)d_in[30]; wmlp=(const float*)d_in[31]; bmlp=(const float*)d_in[32];
    } else if (n_in >= 33) {
        alpha=(const float*)d_in[0]; b20=(const float*)d_in[1]; b_in=(const float*)d_in[2];
        bm0=(const float*)d_in[3]; bmlp=(const float*)d_in[4];
        for (int l = 0; l < 4; l++) {
            eqb[l] =(const float*)d_in[5+l];  eqbd[l]=(const float*)d_in[9+l];
            eqw[l] =(const float*)d_in[13+l]; msgb[l]=(const float*)d_in[18+l];
            msgw[l]=(const float*)d_in[22+l];
        }
        momenta=(const float*)d_in[17]; nobj=(const int*)d_in[26]; scalars=(const float*)d_in[27];
        w20=(const float*)d_in[28]; w_in=(const float*)d_in[29]; w_lin=(const float*)d_in[30];
        wm0=(const float*)d_in[31]; wmlp=(const float*)d_in[32];
    } else {
        momenta=(const float*)d_in[0]; scalars=(const float*)d_in[1]; nobj=(const int*)d_in[2];
        w_lin=(const float*)d_in[3]; alpha=(const float*)d_in[4]; w_in=(const float*)d_in[5];
        b_in=(const float*)d_in[6];
        for (int l = 0; l < 4; l++) {
            msgw[l]=(const float*)d_in[7]+(size_t)l*C_*C_;     msgb[l]=(const float*)d_in[8]+(size_t)l*C_;
            eqw[l] =(const float*)d_in[9]+(size_t)l*15*C_*C_;  eqb[l] =(const float*)d_in[10]+(size_t)l*C_;
            eqbd[l]=(const float*)d_in[11]+(size_t)l*C_;
        }
        wm0=(const float*)d_in[12]; bm0=(const float*)d_in[13]; w20=(const float*)d_in[14];
        b20=(const float*)d_in[15]; wmlp=(const float*)d_in[16]; bmlp=(const float*)d_in[17];
    }

    cudaFuncSetAttribute(k_gemm0, cudaFuncAttributeMaxDynamicSharedMemorySize, SM_G0);
    cudaFuncSetAttribute(k_gemm2, cudaFuncAttributeMaxDynamicSharedMemorySize, SM_G);
    cudaFuncSetAttribute(k_proj,  cudaFuncAttributeMaxDynamicSharedMemorySize, SM_P);

    __nv_bfloat16 *Ahi=0, *Alo=0, *Bhi=0, *Blo=0;
    uint4 *Bf=0, *Pf=0;
    cudaGetSymbolAddress((void**)&Ahi, g_Ahi);
    cudaGetSymbolAddress((void**)&Alo, g_Alo);
    cudaGetSymbolAddress((void**)&Bhi, g_Bhi);
    cudaGetSymbolAddress((void**)&Blo, g_Blo);
    cudaGetSymbolAddress((void**)&Bf,  g_Bf);
    cudaGetSymbolAddress((void**)&Pf,  g_Pf);

    k_setup<<<132, 256>>>(msgw[0], msgw[1], msgw[2], msgw[3],
                          eqw[0], eqw[1], eqw[2], eqw[3], wm0,
                          scalars, nobj, w_in);

    k_gemm0<<<TILES, 256, SM_G0>>>(momenta, w_lin, alpha, b_in,
                                   Bf + 0*4096, msgb[0], nobj, Bhi, Blo);

    __nv_bfloat16 *curHi = Bhi, *curLo = Blo, *nxtHi = Ahi, *nxtLo = Alo;
    for (int l = 0; l < 4; l++) {
        k_r1c<<<B_*N_, 256>>>(curHi, curLo, nobj);
        k_proj<<<80, 256, SM_P>>>(Pf + (size_t)(l*3)*12288,
                                  eqw[l], eqb[l], eqbd[l], nobj);
        if (l < 3) {
            k_gemm2<<<TILES, 256, SM_G>>>(curHi, curLo,
                                          Bf + (4 + l*2)*4096, Bf + (5 + l*2)*4096,
                                          Bf + (l+1)*4096, msgb[l+1], nobj, 0,
                                          nxtHi, nxtLo);
            __nv_bfloat16* th = curHi; curHi = nxtHi; nxtHi = th;
            __nv_bfloat16* tl = curLo; curLo = nxtLo; nxtLo = tl;
        } else {
            k_gemm2<<<TILES, 256, SM_G>>>(curHi, curLo,
                                          Bf + (4 + l*2)*4096, Bf + (5 + l*2)*4096,
                                          Bf + 12*4096, bm0, nobj, 3,
                                          (__nv_bfloat16*)0, (__nv_bfloat16*)0);
        }
    }

    k_out<<<B_, 128>>>(w20, b20, wmlp, bmlp, (float*)d_out);
}

// round 17
// speedup vs baseline: 1.1938x; 1.0345x over previous
#include <cuda_runtime.h>
#include <cuda_bf16.h>
#include <math.h>
#include <stdint.h>

#define B_  32
#define N_  64
#define S_  9
#define C_  128
#define CS_ 32
#define AVGF 49.0f
#define TILES (B_*32)

// ---------------- device scratch ----------------
__device__ __nv_bfloat16 g_Ahi[TILES*16384], g_Alo[TILES*16384];
__device__ __nv_bfloat16 g_Bhi[TILES*16384], g_Blo[TILES*16384];
__device__ __nv_bfloat16 g_Xhi[B_*N_*384], g_Xlo[B_*N_*384];
__device__ uint4 g_Bf[13*4096];
__device__ uint4 g_Pf[12*12288];
__device__ float g_y012[B_*N_*3*CS_];
__device__ float g_y34[B_*2*CS_];
__device__ float g_Vrow[B_*N_*C_];
__device__ float g_Vcol[B_*N_*C_];
__device__ float g_Dd[B_*N_*C_];
__device__ float g_G[B_*C_];
__device__ float g_E[B_*C_];
__device__ float g_dg[B_*C_];
__device__ float g_tot[B_*C_];

__device__ __forceinline__ float lrelu(float x){ return x >= 0.f ? x : 0.01f*x; }
__device__ __forceinline__ uint32_t smem_u32(const void* p) {
    uint32_t a;
    asm("{ .reg .u64 t; cvta.to.shared.u64 t, %1; cvt.u32.u64 %0, t; }" : "=r"(a) : "l"(p));
    return a;
}
__device__ __forceinline__ void split2(float v, __nv_bfloat16& h, __nv_bfloat16& l) {
    h = __float2bfloat16(v);
    l = __float2bfloat16(v - __bfloat162float(h));
}
__device__ __forceinline__ uint32_t packbf(__nv_bfloat16 a, __nv_bfloat16 b) {
    __nv_bfloat162 p; p.x = a; p.y = b;
    return *(uint32_t*)&p;
}
__device__ __forceinline__ void ldmx4(uint32_t a, uint32_t& r0, uint32_t& r1, uint32_t& r2, uint32_t& r3) {
    asm volatile("ldmatrix.sync.aligned.m8n8.x4.shared.b16 {%0,%1,%2,%3}, [%4];"
                 : "=r"(r0), "=r"(r1), "=r"(r2), "=r"(r3) : "r"(a));
}
__device__ __forceinline__ void mma16816(float* c, const uint32_t* a, uint32_t b0, uint32_t b1) {
    asm volatile("mma.sync.aligned.m16n8k16.row.col.f32.bf16.bf16.f32 "
                 "{%0,%1,%2,%3}, {%4,%5,%6,%7}, {%8,%9}, {%0,%1,%2,%3};"
                 : "+f"(c[0]), "+f"(c[1]), "+f"(c[2]), "+f"(c[3])
                 : "r"(a[0]), "r"(a[1]), "r"(a[2]), "r"(a[3]), "r"(b0), "r"(b1));
}
#define CPA16(dst, src) asm volatile("cp.async.ca.shared.global [%0], [%1], 16;" :: "r"(dst), "l"(src))
#define CPCOMMIT() asm volatile("cp.async.commit_group;" ::: "memory")
#define CPWAIT1()  asm volatile("cp.async.wait_group 1;"  ::: "memory")
#define CPWAIT()   asm volatile("cp.async.wait_group 0;"  ::: "memory")

#define ALO2  34816
#define SM_G  69632
#define SM_G0 81920
#define PROW  784
#define ALOP  50176
#define SM_P  100352

// ---------------- one-time setup ----------------
__global__ void k_setup(const float* __restrict__ m0, const float* __restrict__ m1,
                        const float* __restrict__ m2, const float* __restrict__ m3,
                        const float* __restrict__ e0, const float* __restrict__ e1,
                        const float* __restrict__ e2, const float* __restrict__ e3,
                        const float* __restrict__ wfin,
                        const float* __restrict__ scalars, const int* __restrict__ nobj,
                        const float* __restrict__ w_in) {
    int blk = blockIdx.x, tid = threadIdx.x;
    if (blk < 52) {
        int mat = blk >> 2, quar = blk & 3;
        const float* W;
        if (mat < 4)       W = (mat==0)?m0:(mat==1)?m1:(mat==2)?m2:m3;
        else if (mat < 12) {
            int l = (mat-4)>>1, wh = (mat-4)&1;
            const float* E = (l==0)?e0:(l==1)?e1:(l==2)?e2:e3;
            W = E + wh*16384;
        } else W = wfin;
        uint4* dst = g_Bf + mat*4096;
        for (int e = quar*1024 + tid; e < quar*1024 + 1024; e += 256) {
            int lane = e&31, nt = (e>>5)&7, ks = (e>>8)&7, wx = e>>11;
            int n = wx*64 + nt*8 + (lane>>2);
            int k0 = ks*16 + (lane&3)*2;
            __nv_bfloat16 h00,l00,h01,l01,h10,l10,h11,l11;
            split2(W[k0*128+n],     h00, l00);
            split2(W[(k0+1)*128+n], h01, l01);
            split2(W[(k0+8)*128+n], h10, l10);
            split2(W[(k0+9)*128+n], h11, l11);
            uint4 o;
            o.x = packbf(h00,h01); o.y = packbf(h10,h11);
            o.z = packbf(l00,l01); o.w = packbf(l10,l11);
            dst[e] = o;
        }
    } else if (blk < 100) {
        int idx = blk - 52;
        int unit = idx >> 2, quar = idx & 3;
        int l = unit / 3, p = unit % 3;
        const int tbl[3][3] = {{3,5,7},{4,6,8},{2,9,10}};
        const float* E = (l==0)?e0:(l==1)?e1:(l==2)?e2:e3;
        uint4* dst = g_Pf + (size_t)unit*12288;
        for (int e = quar*3072 + tid; e < quar*3072 + 3072; e += 256) {
            int wx = e / 6144, rem = e % 6144;
            int ks = rem >> 8, nt = (rem>>5)&7, lane = rem&31;
            int n = wx*64 + nt*8 + (lane>>2);
            int k0 = ks*16 + (lane&3)*2;
            __nv_bfloat16 hh[4], ll[4];
            #pragma unroll
            for (int q = 0; q < 4; q++) {
                int k = k0 + (q>>1)*8 + (q&1);
                int mat = tbl[p][k>>7], kk = k&127;
                split2(E[(mat*C_ + kk)*C_ + n], hh[q], ll[q]);
            }
            uint4 o;
            o.x = packbf(hh[0],hh[1]); o.y = packbf(hh[2],hh[3]);
            o.z = packbf(ll[0],ll[1]); o.w = packbf(ll[2],ll[3]);
            dst[e] = o;
        }
    } else {
        int b = blk - 100;
        __shared__ float xs[N_][S_];
        __shared__ float ssum[S_];
        int nb = nobj[b];
        for (int idx = tid; idx < N_*S_; idx += 256) {
            int n = idx/S_, s = idx%S_;
            xs[n][s] = (n < nb) ? scalars[(b*N_+n)*S_+s] : 0.f;
        }
        __syncthreads();
        if (tid < S_) {
            float a = 0.f;
            for (int n = 0; n < N_; n++) a += xs[n][tid];
            ssum[tid] = a / AVGF;
        }
        __syncthreads();
        for (int idx = tid; idx < N_*CS_; idx += 256) {
            int n = idx/CS_, c = idx%CS_;
            float a0=0, a1=0, a2=0;
            #pragma unroll
            for (int s = 0; s < S_; s++) {
                float xv = xs[n][s];
                a0 += xv*w_in[(0*S_+s)*CS_+c];
                a1 += xv*w_in[(1*S_+s)*CS_+c];
                a2 += xv*w_in[(2*S_+s)*CS_+c];
            }
            g_y012[((b*N_+n)*3+0)*CS_+c] = a0;
            g_y012[((b*N_+n)*3+1)*CS_+c] = a1;
            g_y012[((b*N_+n)*3+2)*CS_+c] = a2;
        }
        if (tid < 2*CS_) {
            int k = tid/CS_, c = tid%CS_;
            float a = 0.f;
            #pragma unroll
            for (int s = 0; s < S_; s++) a += ssum[s]*w_in[((3+k)*S_+s)*CS_+c];
            g_y34[(b*2+k)*CS_+c] = a;
        }
    }
}

// ---------------- GEMM helpers ----------------
struct GemmCtx {
    uint32_t sb;
    int tid, wid, lane, tile, b, i0, nb;
    int wy, wx, rb, nb0, lrow, lcolb, g, t2;
};
__device__ __forceinline__ void stage_src(const GemmCtx& X, const __nv_bfloat16* Ahi,
                                          const __nv_bfloat16* Alo, bool transp) {
    #pragma unroll
    for (int uu = 0; uu < 16; uu++) {
        int group = uu>>3, comp = (uu>>2)&1, sub = uu&3;
        int f = X.tid + 256*(comp*8 + group*4 + sub);
        int idx = f & 2047;
        int row = (idx>>3)&127, c8 = idx&7, c16 = group*8 + c8;
        const __nv_bfloat16* basep = comp ? Alo : Ahi;
        size_t goff;
        if (!transp) {
            goff = (size_t)X.tile*16384 + row*128 + c16*8;
        } else {
            int jj = row&63, hh = row>>6;
            goff = ((size_t)(X.b*32 + (jj>>1))*128 + (jj&1)*64 + X.i0 + hh)*128 + c16*8;
        }
        uint32_t dst = X.sb + comp*ALO2 + row*272 + c16*16;
        CPA16(dst, basep + goff);
        if (uu == 7) CPCOMMIT();
    }
    CPCOMMIT();
}
__device__ __forceinline__ void compute_pass(const GemmCtx& X, const uint4* Fw,
                                             float c[2][8][4], bool staged) {
    #pragma unroll
    for (int half = 0; half < 2; half++) {
        if (staged) { if (half == 0) CPWAIT1(); else CPWAIT(); __syncthreads(); }
        #pragma unroll
        for (int ks = half*4; ks < half*4+4; ks++) {
            uint32_t ah[2][4], al[2][4];
            #pragma unroll
            for (int mt = 0; mt < 2; mt++) {
                uint32_t adr = X.sb + (X.rb + mt*16 + X.lrow)*272 + ks*32 + X.lcolb;
                ldmx4(adr, ah[mt][0], ah[mt][1], ah[mt][2], ah[mt][3]);
                adr += ALO2;
                ldmx4(adr, al[mt][0], al[mt][1], al[mt][2], al[mt][3]);
            }
            uint4 f4 = Fw[(ks*8)*32 + X.lane];
            #pragma unroll
            for (int nt = 0; nt < 8; nt++) {
                uint4 cur = f4;
                if (nt < 7) f4 = Fw[(ks*8 + nt + 1)*32 + X.lane];
                #pragma unroll
                for (int mt = 0; mt < 2; mt++) {
                    mma16816(c[mt][nt], ah[mt], cur.x, cur.y);
                    mma16816(c[mt][nt], ah[mt], cur.z, cur.w);
                    mma16816(c[mt][nt], al[mt], cur.x, cur.y);
                }
            }
        }
    }
}
__device__ __forceinline__ void init_ctx(GemmCtx& X, unsigned char* sm) {
    X.sb = smem_u32(sm);
    X.tid = threadIdx.x; X.wid = X.tid>>5; X.lane = X.tid&31;
    X.tile = blockIdx.x; X.b = X.tile>>5; X.i0 = (X.tile&31)<<1;
    X.wy = X.wid&3; X.wx = X.wid>>2;
    X.rb = X.wy*32; X.nb0 = X.wx*64;
    X.lrow = (X.lane&7) + ((X.lane>>3)&1)*8;
    X.lcolb = ((X.lane>>4)&1)*16;
    X.g = X.lane>>2; X.t2 = (X.lane&3)*2;
}
#define ZEROC(c) { _Pragma("unroll") for (int mt=0;mt<2;mt++) _Pragma("unroll") for (int nt=0;nt<8;nt++) _Pragma("unroll") for (int q=0;q<4;q++) c[mt][nt][q]=0.f; }

// epilogue: write U (bf16 hi/lo) + rvec/dvec into X (atomic-free; tile-local)
__device__ __forceinline__ void epilogue_UX(const GemmCtx& X, float c[2][8][4],
                                            const float* bias,
                                            __nv_bfloat16* OutHi, __nv_bfloat16* OutLo,
                                            unsigned char* sm) {
    __syncthreads();
    float* Vs = (float*)sm;   // [128][132]
    __nv_bfloat16* Hi = OutHi + (size_t)X.tile*16384;
    __nv_bfloat16* Lo = OutLo + (size_t)X.tile*16384;
    #pragma unroll
    for (int mt = 0; mt < 2; mt++)
        #pragma unroll
        for (int h = 0; h < 2; h++) {
            int row = X.rb + mt*16 + X.g + h*8;
            int i = X.i0 + (row>>6), j = row&63;
            float mask = (i < X.nb && j < X.nb) ? 1.f : 0.f;
            #pragma unroll
            for (int nt = 0; nt < 8; nt++) {
                int col = X.nb0 + nt*8 + X.t2;
                float vx = lrelu(c[mt][nt][h*2+0] + bias[col])   * mask;
                float vy = lrelu(c[mt][nt][h*2+1] + bias[col+1]) * mask;
                __nv_bfloat16 hx,lx,hy,ly;
                split2(vx, hx, lx); split2(vy, hy, ly);
                *(uint32_t*)(Hi + row*128 + col) = packbf(hx, hy);
                *(uint32_t*)(Lo + row*128 + col) = packbf(lx, ly);
                float2 v; v.x = vx; v.y = vy;
                *(float2*)(Vs + row*132 + col) = v;
            }
        }
    __syncthreads();
    int t = X.tid;
    int half = t >> 7, cc = t & 127;
    float s = 0.f;
    #pragma unroll 8
    for (int r = 0; r < 64; r++) s += Vs[(half*64 + r)*132 + cc];
    size_t m = (size_t)(X.b*64 + X.i0 + half);
    __nv_bfloat16 h, l;
    split2(s / AVGF, h, l);
    g_Xhi[m*384 + 128 + cc] = h; g_Xlo[m*384 + 128 + cc] = l;
    split2(Vs[(half*64 + X.i0 + half)*132 + cc], h, l);
    g_Xhi[m*384 + cc] = h; g_Xlo[m*384 + cc] = l;
}

// ---------------- mode-0 GEMM with fused T-init (no global T) ----------------
__global__ void __launch_bounds__(256, 2) k_gemm0(const float* __restrict__ momenta,
                                                  const float* __restrict__ w_lin,
                                                  const float* __restrict__ alpha,
                                                  const float* __restrict__ b_in,
                                                  const uint4* __restrict__ F,
                                                  const float* __restrict__ bias,
                                                  const int* __restrict__ nobj,
                                                  __nv_bfloat16* __restrict__ OutHi,
                                                  __nv_bfloat16* __restrict__ OutLo) {
    extern __shared__ unsigned char sm[];
    GemmCtx X; init_ctx(X, sm);
    X.nb = nobj[X.b];
    if (X.i0 >= X.nb) return;
    int tid = X.tid, b = X.b, i0 = X.i0, nb = X.nb;
    float* aux = (float*)(sm + SM_G);
    float* pm  = aux;
    float* dij = aux + 256;
    float* y1s = aux + 384;
    float* y0r = aux + 2432;
    float* y2r = aux + 2496;
    float* y3s = aux + 2560;
    float* y4s = aux + 2592;
    pm[tid] = momenta[b*256 + tid];
    for (int idx = tid; idx < 2048; idx += 256)
        y1s[idx] = g_y012[((b*64 + (idx>>5))*3 + 1)*32 + (idx&31)];
    if (tid < 64) {
        int h = tid>>5, c = tid&31;
        y0r[tid] = g_y012[((b*64+i0+h)*3+0)*32+c];
        y2r[tid] = g_y012[((b*64+i0+h)*3+2)*32+c];
    } else if (tid < 96) {
        y3s[tid-64] = g_y34[(b*2+0)*32 + tid-64];
    } else if (tid < 128) {
        y4s[tid-96] = g_y34[(b*2+1)*32 + tid-96];
    }
    __syncthreads();
    if (tid < 128) {
        int h = tid>>6, j = tid&63;
        const float* pi = pm + (i0+h)*4;
        const float* pj = pm + j*4;
        dij[tid] = pi[0]*pj[0] - pi[1]*pj[1] - pi[2]*pj[2] - pi[3]*pj[3];
    }
    __syncthreads();
    {
        int c2 = tid & 63, rh = tid >> 6;
        int c0 = c2*2;
        int h = rh >> 1, i = i0 + h;
        bool iact = (i < nb);
        float bx=0, by=0, d2x=0, d2y=0, wlx=0, wly=0, alx=0, aly=0;
        if (c2 < 16) {
            bx = y0r[h*32+c0]   + y3s[c0]   + b_in[c0];
            by = y0r[h*32+c0+1] + y3s[c0+1] + b_in[c0+1];
            d2x = y2r[h*32+c0]   + y4s[c0];
            d2y = y2r[h*32+c0+1] + y4s[c0+1];
        } else {
            wlx = w_lin[c0-32]; wly = w_lin[c0-31];
            alx = alpha[c0-32]; aly = alpha[c0-31];
        }
        #pragma unroll 4
        for (int it = 0; it < 32; it++) {
            int j = (rh&1)*32 + it;
            int row = h*64 + j;
            float mask = (iact && j < nb) ? 1.f : 0.f;
            float vx, vy;
            if (c2 < 16) {
                vx = bx + y1s[j*32+c0];
                vy = by + y1s[j*32+c0+1];
                if (j == i) { vx += d2x; vy += d2y; }
                vx = lrelu(vx) * mask;
                vy = lrelu(vy) * mask;
            } else {
                float d = dij[h*64+j];
                float rx = d*wlx, ry = d*wly;
                vx = alx * copysignf(log1pf(fabsf(rx)), rx) * mask;
                vy = aly * copysignf(log1pf(fabsf(ry)), ry) * mask;
            }
            __nv_bfloat16 hx,lx,hy,ly;
            split2(vx, hx, lx); split2(vy, hy, ly);
            *(uint32_t*)(sm + row*272 + c0*2)        = packbf(hx, hy);
            *(uint32_t*)(sm + ALO2 + row*272 + c0*2) = packbf(lx, ly);
        }
    }
    __syncthreads();
    float c[2][8][4]; ZEROC(c);
    compute_pass(X, F + X.wx*2048, c, false);
    epilogue_UX(X, c, bias, OutHi, OutLo, sm);
}

// ---------------- fused GEMM: Eq2to2 dual + combine -> T(smem) -> next GEMM ----------
__global__ void __launch_bounds__(256, 2) k_gemm2(const __nv_bfloat16* __restrict__ Uhi,
                                                  const __nv_bfloat16* __restrict__ Ulo,
                                                  const uint4* __restrict__ F0,
                                                  const uint4* __restrict__ F1,
                                                  const uint4* __restrict__ F2,
                                                  const float* __restrict__ bias2,
                                                  const int* __restrict__ nobj, int mode2,
                                                  __nv_bfloat16* __restrict__ OutHi,
                                                  __nv_bfloat16* __restrict__ OutLo) {
    extern __shared__ unsigned char sm[];
    GemmCtx X; init_ctx(X, sm);
    X.nb = nobj[X.b];
    if (X.i0 >= X.nb) return;
    float c[2][8][4]; ZEROC(c);
    stage_src(X, Uhi, Ulo, false);
    compute_pass(X, F0 + X.wx*2048, c, true);
    __syncthreads();
    stage_src(X, Uhi, Ulo, true);
    compute_pass(X, F1 + X.wx*2048, c, true);
    __syncthreads();
    #pragma unroll
    for (int mt = 0; mt < 2; mt++)
        #pragma unroll
        for (int h = 0; h < 2; h++) {
            int row = X.rb + mt*16 + X.g + h*8;
            int i = X.i0 + (row>>6), j = row&63;
            float mask = (i < X.nb && j < X.nb) ? 1.f : 0.f;
            bool diag = (i == j);
            const float* vr = g_Vrow + (X.b*64+i)*C_;
            const float* vc = g_Vcol + (X.b*64+j)*C_;
            const float* gg = g_G + X.b*C_;
            const float* dd = g_Dd + (X.b*64+i)*C_;
            const float* ee = g_E + X.b*C_;
            #pragma unroll
            for (int nt = 0; nt < 8; nt++) {
                int col = X.nb0 + nt*8 + X.t2;
                float vx = c[mt][nt][h*2+0] + vr[col]   + gg[col]   + vc[col];
                float vy = c[mt][nt][h*2+1] + vr[col+1] + gg[col+1] + vc[col+1];
                if (diag) { vx += dd[col] + ee[col]; vy += dd[col+1] + ee[col+1]; }
                vx = lrelu(vx) * mask;
                vy = lrelu(vy) * mask;
                __nv_bfloat16 hx,lx,hy,ly;
                split2(vx, hx, lx); split2(vy, hy, ly);
                *(uint32_t*)(sm + row*272 + col*2)        = packbf(hx, hy);
                *(uint32_t*)(sm + ALO2 + row*272 + col*2) = packbf(lx, ly);
            }
        }
    __syncthreads();
    ZEROC(c);
    compute_pass(X, F2 + X.wx*2048, c, false);
    if (mode2 == 0) {
        epilogue_UX(X, c, bias2, OutHi, OutLo, sm);
    } else {
        __syncthreads();
        float* Vs = (float*)sm;
        #pragma unroll
        for (int mt = 0; mt < 2; mt++)
            #pragma unroll
            for (int h = 0; h < 2; h++) {
                int row = X.rb + mt*16 + X.g + h*8;
                int i = X.i0 + (row>>6), j = row&63;
                float mask = (i < X.nb && j < X.nb) ? 1.f : 0.f;
                #pragma unroll
                for (int nt = 0; nt < 8; nt++) {
                    int col = X.nb0 + nt*8 + X.t2;
                    float2 v;
                    v.x = lrelu(c[mt][nt][h*2+0] + bias2[col])   * mask;
                    v.y = lrelu(c[mt][nt][h*2+1] + bias2[col+1]) * mask;
                    *(float2*)(Vs + row*132 + col) = v;
                }
            }
        __syncthreads();
        if (X.tid < 128) {
            float s = 0.f;
            #pragma unroll 8
            for (int r = 0; r < 128; r++) s += Vs[r*132 + X.tid];
            atomicAdd(&g_tot[X.b*C_ + X.tid], s);
            float dgv = Vs[X.i0*132 + X.tid] + Vs[(64 + X.i0 + 1)*132 + X.tid];
            atomicAdd(&g_dg[X.b*C_ + X.tid], dgv);
        }
    }
}

// ---------------- proj GEMM (64-row M tiles, 128 blocks) + fused G/E ----------------
__global__ void __launch_bounds__(256, 1) k_proj(const uint4* __restrict__ Pf,
                                                 const float* __restrict__ W,
                                                 const float* __restrict__ eqb,
                                                 const float* __restrict__ eqbd,
                                                 const int* __restrict__ nobj) {
    extern __shared__ unsigned char sm[];
    if (blockIdx.x >= 96) {
        int b = blockIdx.x - 96, d = threadIdx.x;
        float* tt = (float*)sm;
        float* tg = (float*)sm + 128;
        if (d < 128) {
            int nb = nobj[b];
            float t = 0.f, tr = 0.f;
            for (int i = 0; i < nb; i++) {
                size_t m = (size_t)(b*N_+i);
                t  += __bfloat162float(g_Xhi[m*384 + 128 + d]) + __bfloat162float(g_Xlo[m*384 + 128 + d]);
                tr += __bfloat162float(g_Xhi[m*384 + d])       + __bfloat162float(g_Xlo[m*384 + d]);
            }
            tt[d] = t / AVGF; tg[d] = tr / AVGF;
        }
        __syncthreads();
        if (d < 128) {
            float g = eqb[d], e = eqbd[d];
            for (int c = 0; c < C_; c++) {
                g += tt[c]*W[(11*C_+c)*C_+d] + tg[c]*W[(13*C_+c)*C_+d];
                e += tt[c]*W[(12*C_+c)*C_+d] + tg[c]*W[(14*C_+c)*C_+d];
            }
            g_G[b*C_+d] = g; g_E[b*C_+d] = e;
        }
        return;
    }
    uint32_t sb = smem_u32(sm);
    int tid = threadIdx.x, wid = tid>>5, lane = tid&31;
    int p = blockIdx.x >> 5, tile = blockIdx.x & 31;   // 32 M-tiles of 64 rows
    int wy = wid&3, wx = wid>>2;
    int rb = wy*16, nb0 = wx*64;
    float c2[8][4];
    #pragma unroll
    for (int nt = 0; nt < 8; nt++)
        #pragma unroll
        for (int q = 0; q < 4; q++) c2[nt][q] = 0.f;
    int lrow = (lane&7) + ((lane>>3)&1)*8;
    int lcolb = ((lane>>4)&1)*16;
    // stage A: 64 rows x 384 cols hi/lo, two K-half commit groups
    #pragma unroll
    for (int uu = 0; uu < 24; uu++) {
        int khalf = uu / 12, v = uu % 12;
        int idx = tid + 256*v;               // 0..3071
        int comp = idx / 1536, rem = idx % 1536;
        int row = rem / 24, gr = rem % 24;
        int kg = khalf*24 + gr;
        const __nv_bfloat16* basep = comp ? g_Xlo : g_Xhi;
        size_t goff = (size_t)(tile*64 + row)*384 + kg*8;
        uint32_t dst = sb + comp*ALOP + row*PROW + kg*16;
        CPA16(dst, basep + goff);
        if (uu == 11) CPCOMMIT();
    }
    CPCOMMIT();
    const uint4* Fw = Pf + (size_t)p*12288 + wx*6144;
    #pragma unroll
    for (int half = 0; half < 2; half++) {
        if (half == 0) CPWAIT1(); else CPWAIT();
        __syncthreads();
        #pragma unroll
        for (int ks = half*12; ks < half*12+12; ks++) {
            uint32_t ah[4], al[4];
            uint32_t adr = sb + (rb + lrow)*PROW + ks*32 + lcolb;
            ldmx4(adr, ah[0], ah[1], ah[2], ah[3]);
            adr += ALOP;
            ldmx4(adr, al[0], al[1], al[2], al[3]);
            uint4 f4 = Fw[(ks*8)*32 + lane];
            #pragma unroll
            for (int nt = 0; nt < 8; nt++) {
                uint4 cur = f4;
                if (nt < 7) f4 = Fw[(ks*8 + nt + 1)*32 + lane];
                mma16816(c2[nt], ah, cur.x, cur.y);
                mma16816(c2[nt], ah, cur.z, cur.w);
                mma16816(c2[nt], al, cur.x, cur.y);
            }
        }
    }
    float* Out = (p==0) ? g_Vrow : (p==1) ? g_Vcol : g_Dd;
    int g = lane>>2, t2 = (lane&3)*2;
    #pragma unroll
    for (int h = 0; h < 2; h++) {
        int row = rb + g + h*8;
        int m = tile*64 + row;
        #pragma unroll
        for (int nt = 0; nt < 8; nt++) {
            int col = nb0 + nt*8 + t2;
            float2 v;
            v.x = c2[nt][h*2+0];
            v.y = c2[nt][h*2+1];
            *(float2*)(Out + (size_t)m*128 + col) = v;
        }
    }
}

// ---------------- col-sum reduction only: U -> X cvec (nb-bounded) ----------------
__global__ void k_r1c(const __nv_bfloat16* __restrict__ Uhi,
                      const __nv_bfloat16* __restrict__ Ulo,
                      const int* __restrict__ nobj) {
    int b = blockIdx.x >> 6, i = blockIdx.x & 63;
    int nb = nobj[b];
    if (i >= nb) return;
    int t = threadIdx.x;
    int g = t & 15, jg = t >> 4;
    __shared__ float redC[16][128];
    float aC[8] = {0,0,0,0,0,0,0,0};
    #pragma unroll
    for (int jj = 0; jj < 4; jj++) {
        int j = jg*4 + jj;
        if (j < nb) {
            size_t off = ((size_t)(b*32 + (j>>1))*128 + (j&1)*64 + i)*128 + g*8;
            uint4 h4 = *(const uint4*)(Uhi + off);
            uint4 l4 = *(const uint4*)(Ulo + off);
            const __nv_bfloat16 *hp = (const __nv_bfloat16*)&h4, *lp = (const __nv_bfloat16*)&l4;
            #pragma unroll
            for (int q = 0; q < 8; q++) aC[q] += __bfloat162float(hp[q]) + __bfloat162float(lp[q]);
        }
    }
    #pragma unroll
    for (int q = 0; q < 8; q++) redC[jg][g*8+q] = aC[q];
    __syncthreads();
    if (t < 128) {
        float s = 0.f;
        #pragma unroll
        for (int r = 0; r < 16; r++) s += redC[r][t];
        size_t m = (size_t)(b*N_+i);
        __nv_bfloat16 h, l; split2(s / AVGF, h, l);
        g_Xhi[m*384 + 256 + t] = h; g_Xlo[m*384 + 256 + t] = l;
    }
}

// ---------------- output head (resets accumulators) ----------------
__global__ void k_out(const float* __restrict__ w20, const float* __restrict__ b20,
                      const float* __restrict__ wmlp, const float* __restrict__ bmlp,
                      float* __restrict__ out) {
    int b = blockIdx.x, d = threadIdx.x;
    __shared__ float a0[C_], a1[C_], act[C_];
    a0[d] = lrelu(g_dg[b*C_+d] / AVGF);
    a1[d] = lrelu(g_tot[b*C_+d] / (AVGF*AVGF));
    g_dg[b*C_+d] = 0.f;
    g_tot[b*C_+d] = 0.f;
    __syncthreads();
    float a = b20[d];
    for (int c = 0; c < C_; c++) a += a0[c]*w20[c*C_+d] + a1[c]*w20[(C_+c)*C_+d];
    act[d] = a;
    __syncthreads();
    if (d < 2) {
        float o = bmlp[d];
        for (int k = 0; k < C_; k++) o += act[k]*wmlp[k*2+d];
        out[b*2+d] = o;
    }
}

// ---------------- host ----------------
extern "C" void kernel_launch(void* const* d_in, const int* in_sizes, int n_in,
                              void* d_out, int out_size) {
    const float *momenta=0, *scalars=0, *w_lin=0, *alpha=0, *w_in=0, *b_in=0;
    const int* nobj=0;
    const float *msgw[4], *msgb[4], *eqw[4], *eqb[4], *eqbd[4];
    const float *wm0=0, *bm0=0, *w20=0, *b20=0, *wmlp=0, *bmlp=0;

    if (n_in >= 33 && in_sizes[0] == 8192) {
        momenta=(const float*)d_in[0]; scalars=(const float*)d_in[1]; nobj=(const int*)d_in[2];
        w_lin=(const float*)d_in[3]; alpha=(const float*)d_in[4]; w_in=(const float*)d_in[5];
        b_in=(const float*)d_in[6];
        for (int l = 0; l < 4; l++) {
            msgw[l]=(const float*)d_in[7+l];  msgb[l]=(const float*)d_in[11+l];
            eqw[l] =(const float*)d_in[15+l]; eqb[l] =(const float*)d_in[19+l];
            eqbd[l]=(const float*)d_in[23+l];
        }
        wm0=(const float*)d_in[27]; bm0=(const float*)d_in[28]; w20=(const float*)d_in[29];
        b20=(const float*)d_in[30]; wmlp=(const float*)d_in[31]; bmlp=(const float*)d_in[32];
    } else if (n_in >= 33) {
        alpha=(const float*)d_in[0]; b20=(const float*)d_in[1]; b_in=(const float*)d_in[2];
        bm0=(const float*)d_in[3]; bmlp=(const float*)d_in[4];
        for (int l = 0; l < 4; l++) {
            eqb[l] =(const float*)d_in[5+l];  eqbd[l]=(const float*)d_in[9+l];
            eqw[l] =(const float*)d_in[13+l]; msgb[l]=(const float*)d_in[18+l];
            msgw[l]=(const float*)d_in[22+l];
        }
        momenta=(const float*)d_in[17]; nobj=(const int*)d_in[26]; scalars=(const float*)d_in[27];
        w20=(const float*)d_in[28]; w_in=(const float*)d_in[29]; w_lin=(const float*)d_in[30];
        wm0=(const float*)d_in[31]; wmlp=(const float*)d_in[32];
    } else {
        momenta=(const float*)d_in[0]; scalars=(const float*)d_in[1]; nobj=(const int*)d_in[2];
        w_lin=(const float*)d_in[3]; alpha=(const float*)d_in[4]; w_in=(const float*)d_in[5];
        b_in=(const float*)d_in[6];
        for (int l = 0; l < 4; l++) {
            msgw[l]=(const float*)d_in[7]+(size_t)l*C_*C_;     msgb[l]=(const float*)d_in[8]+(size_t)l*C_;
            eqw[l] =(const float*)d_in[9]+(size_t)l*15*C_*C_;  eqb[l] =(const float*)d_in[10]+(size_t)l*C_;
            eqbd[l]=(const float*)d_in[11]+(size_t)l*C_;
        }
        wm0=(const float*)d_in[12]; bm0=(const float*)d_in[13]; w20=(const float*)d_in[14];
        b20=(const float*)d_in[15]; wmlp=(const float*)d_in[16]; bmlp=(const float*)d_in[17];
    }

    cudaFuncSetAttribute(k_gemm0, cudaFuncAttributeMaxDynamicSharedMemorySize, SM_G0);
    cudaFuncSetAttribute(k_gemm2, cudaFuncAttributeMaxDynamicSharedMemorySize, SM_G);
    cudaFuncSetAttribute(k_proj,  cudaFuncAttributeMaxDynamicSharedMemorySize, SM_P);

    __nv_bfloat16 *Ahi=0, *Alo=0, *Bhi=0, *Blo=0;
    uint4 *Bf=0, *Pf=0;
    cudaGetSymbolAddress((void**)&Ahi, g_Ahi);
    cudaGetSymbolAddress((void**)&Alo, g_Alo);
    cudaGetSymbolAddress((void**)&Bhi, g_Bhi);
    cudaGetSymbolAddress((void**)&Blo, g_Blo);
    cudaGetSymbolAddress((void**)&Bf,  g_Bf);
    cudaGetSymbolAddress((void**)&Pf,  g_Pf);

    k_setup<<<132, 256>>>(msgw[0], msgw[1], msgw[2], msgw[3],
                          eqw[0], eqw[1], eqw[2], eqw[3], wm0,
                          scalars, nobj, w_in);

    k_gemm0<<<TILES, 256, SM_G0>>>(momenta, w_lin, alpha, b_in,
                                   Bf + 0*4096, msgb[0], nobj, Bhi, Blo);

    __nv_bfloat16 *curHi = Bhi, *curLo = Blo, *nxtHi = Ahi, *nxtLo = Alo;
    for (int l = 0; l < 4; l++) {
        k_r1c<<<B_*N_, 256>>>(curHi, curLo, nobj);
        k_proj<<<128, 256, SM_P>>>(Pf + (size_t)(l*3)*12288,
                                   eqw[l], eqb[l], eqbd[l], nobj);
        if (l < 3) {
            k_gemm2<<<TILES, 256, SM_G>>>(curHi, curLo,
                                          Bf + (4 + l*2)*4096, Bf + (5 + l*2)*4096,
                                          Bf + (l+1)*4096, msgb[l+1], nobj, 0,
                                          nxtHi, nxtLo);
            __nv_bfloat16* th = curHi; curHi = nxtHi; nxtHi = th;
            __nv_bfloat16* tl = curLo; curLo = nxtLo; nxtLo = tl;
        } else {
            k_gemm2<<<TILES, 256, SM_G>>>(curHi, curLo,
                                          Bf + (4 + l*2)*4096, Bf + (5 + l*2)*4096,
                                          Bf + 12*4096, bm0, nobj, 3,
                                          (__nv_bfloat16*)0, (__nv_bfloat16*)0);
        }
    }

    k_out<<<B_, 128>>>(w20, b20, wmlp, bmlp, (float*)d_out);
}